// round 13
// baseline (speedup 1.0000x reference)
#include <cuda_runtime.h>
#include <cuda_bf16.h>
#include <cstdint>

// ---------------------------------------------------------------------------
// GAT R12: node_agg e-value smem caching (skips el re-gather for deg<=64,
// avg deg = 16); gemm_dual Wl-fill hoisted over phase-1 epilogue. Core = R11.
// ---------------------------------------------------------------------------

#define NMAX 50000
#define EMAX 800000
#define SLOPE 0.2f
#define BN_EPS 1e-5f
#define NEG_INF (-1e30f)
#define WS (160 * 128)

// ---------------- scratch ----------------
__device__ __align__(16) float g_z  [NMAX * 160];
__device__ __align__(16) float g_bufA[NMAX * 160];
__device__ __align__(16) float g_bufB[NMAX * 128];
__device__ __align__(16) float g_el [NMAX * 4];
__device__ __align__(16) float g_er [NMAX * 4];
__device__ __align__(16) float g_bnsumA[256];
__device__ __align__(16) float g_bnsumB[256];
__device__ int g_deg[NMAX];
__device__ int g_rowptr[NMAX + 1];
__device__ int g_wcur[NMAX];
__device__ int g_csrsrc[EMAX];
__device__ int g_bsum[64];
__device__ __align__(16) __nv_bfloat16 g_wthi[6][WS];
__device__ __align__(16) __nv_bfloat16 g_wtlo[6][WS];

__device__ __forceinline__ uint32_t smem_u32(const void* p) {
    uint32_t a;
    asm("{ .reg .u64 t; cvta.to.shared.u64 t, %1; cvt.u32.u64 %0, t; }" : "=r"(a) : "l"(p));
    return a;
}
__device__ __forceinline__ float lrelu(float x) { return x >= 0.f ? x : SLOPE * x; }

__device__ __forceinline__ void ldmx4(uint32_t* r, uint32_t addr) {
    asm volatile("ldmatrix.sync.aligned.m8n8.x4.shared.b16 {%0,%1,%2,%3}, [%4];"
                 : "=r"(r[0]), "=r"(r[1]), "=r"(r[2]), "=r"(r[3]) : "r"(addr));
}
__device__ __forceinline__ void ldmx2(uint32_t* r, uint32_t addr) {
    asm volatile("ldmatrix.sync.aligned.m8n8.x2.shared.b16 {%0,%1}, [%2];"
                 : "=r"(r[0]), "=r"(r[1]) : "r"(addr));
}
__device__ __forceinline__ void mma16816(float* c, const uint32_t* a, const uint32_t* b) {
    asm volatile(
        "mma.sync.aligned.m16n8k16.row.col.f32.bf16.bf16.f32 "
        "{%0,%1,%2,%3}, {%4,%5,%6,%7}, {%8,%9}, {%0,%1,%2,%3};"
        : "+f"(c[0]), "+f"(c[1]), "+f"(c[2]), "+f"(c[3])
        : "r"(a[0]), "r"(a[1]), "r"(a[2]), "r"(a[3]), "r"(b[0]), "r"(b[1]));
}

// ================= wsplit_all: 6 weight matrices + zero deg/bnsum ===========
__global__ void wsplit_all(const float* __restrict__ W0, const float* __restrict__ W1,
                           const float* __restrict__ W2, const float* __restrict__ W3,
                           const float* __restrict__ W4, const float* __restrict__ W5,
                           __nv_bfloat16* __restrict__ hi, __nv_bfloat16* __restrict__ lo,
                           int* __restrict__ deg, float* __restrict__ bnA,
                           float* __restrict__ bnB, int n) {
    int i = blockIdx.x * blockDim.x + threadIdx.x;
    if (i < n) deg[i] = 0;
    if (i < 256) { bnA[i] = 0.f; bnB[i] = 0.f; }
    if (i < 106496) {
        int m, base, N;
        if (i < 65536)      { m = i >> 14; base = m << 14; N = 128; }
        else if (i < 86016) { m = 4; base = 65536; N = 160; }
        else                { m = 5; base = 86016; N = 160; }
        int k = i - base;
        int nn = k >> 7, kk = k & 127;
        const float* W = (m == 0) ? W0 : (m == 1) ? W1 : (m == 2) ? W2
                       : (m == 3) ? W3 : (m == 4) ? W4 : W5;
        float v = W[kk * N + nn];
        __nv_bfloat16 h = __float2bfloat16(v);
        hi[m * WS + k] = h;
        lo[m * WS + k] = __float2bfloat16(v - __bfloat162float(h));
    }
}

// ================= dual GEMM =================
template <int N, int FOUT, bool BNIN>
__global__ void __launch_bounds__(256, 1)
gemm_dual(const float* __restrict__ X,
          const __nv_bfloat16* __restrict__ Bc_hi, const __nv_bfloat16* __restrict__ Bc_lo,
          const __nv_bfloat16* __restrict__ Bl_hi, const __nv_bfloat16* __restrict__ Bl_lo,
          const float* __restrict__ bcbias,
          const float* __restrict__ bnsum, const float* __restrict__ bng,
          const float* __restrict__ bnb,
          float* __restrict__ z, float* __restrict__ out,
          const float* __restrict__ al, const float* __restrict__ ar,
          float* __restrict__ el, float* __restrict__ er, int n) {
    constexpr int LDA = 136;
    constexpr int NF = N / 16;
    extern __shared__ __align__(16) char smem[];
    __nv_bfloat16* sAh = (__nv_bfloat16*)smem;
    __nv_bfloat16* sAl = sAh + 128 * LDA;
    __nv_bfloat16* sBh = sAl + 128 * LDA;
    __nv_bfloat16* sBl = sBh + N * LDA;
    __shared__ float s_bn[256];

    const int tid = threadIdx.x;
    const int wid = tid >> 5;
    const int lane = tid & 31;
    const int wm = wid & 3;
    const int wn = wid >> 2;
    const int quad = lane >> 2, tq = lane & 3;
    const int row0 = blockIdx.x * 128;

    if (BNIN) {
        if (tid < 128) {
            float inv_n = 1.f / (float)n;
            float mean = bnsum[tid] * inv_n;
            float var = bnsum[128 + tid] * inv_n - mean * mean;
            float s = bng[tid] * rsqrtf(var + BN_EPS);
            s_bn[tid] = s;
            s_bn[128 + tid] = bnb[tid] - mean * s;
        }
        __syncthreads();
    }

    // ---- fill A (fp32 -> bf16 hi/lo; optional BN+ReLU) ----
    for (int idx = tid; idx < 128 * 32; idx += 256) {
        int r = idx >> 5, c4 = idx & 31;
        int gr = row0 + r;
        float4 v = make_float4(0.f, 0.f, 0.f, 0.f);
        if (gr < n) {
            v = *(const float4*)&X[gr * 128 + c4 * 4];
            if (BNIN) {
                int c = c4 * 4;
                v.x = fmaxf(0.f, fmaf(v.x, s_bn[c + 0], s_bn[128 + c + 0]));
                v.y = fmaxf(0.f, fmaf(v.y, s_bn[c + 1], s_bn[128 + c + 1]));
                v.z = fmaxf(0.f, fmaf(v.z, s_bn[c + 2], s_bn[128 + c + 2]));
                v.w = fmaxf(0.f, fmaf(v.w, s_bn[c + 3], s_bn[128 + c + 3]));
            }
        }
        __nv_bfloat162 h01, h23, l01, l23;
        h01.x = __float2bfloat16(v.x); l01.x = __float2bfloat16(v.x - __bfloat162float(h01.x));
        h01.y = __float2bfloat16(v.y); l01.y = __float2bfloat16(v.y - __bfloat162float(h01.y));
        h23.x = __float2bfloat16(v.z); l23.x = __float2bfloat16(v.z - __bfloat162float(h23.x));
        h23.y = __float2bfloat16(v.w); l23.y = __float2bfloat16(v.w - __bfloat162float(h23.y));
        uint2 hu, lu;
        hu.x = *(uint32_t*)&h01; hu.y = *(uint32_t*)&h23;
        lu.x = *(uint32_t*)&l01; lu.y = *(uint32_t*)&l23;
        *(uint2*)&sAh[r * LDA + c4 * 4] = hu;
        *(uint2*)&sAl[r * LDA + c4 * 4] = lu;
    }
    // ---- fill B = Wc (hi+lo) ----
    for (int idx = tid; idx < N * 16; idx += 256) {
        int r = idx >> 4, c = idx & 15;
        *(uint4*)&sBh[r * LDA + c * 8] = *(const uint4*)&Bc_hi[r * 128 + c * 8];
        *(uint4*)&sBl[r * LDA + c * 8] = *(const uint4*)&Bc_lo[r * 128 + c * 8];
    }
    __syncthreads();

    const uint32_t uAh = smem_u32(sAh), uAl = smem_u32(sAl);
    const uint32_t uBh = smem_u32(sBh), uBl = smem_u32(sBl);
    const int arow = wm * 32 + (lane & 15);
    const int acol8 = (lane >> 4) * 8;
    const int brow = wn * (N / 2) + (lane & 7);
    const int bcol8 = ((lane >> 3) & 1) * 8;

    float c[2][NF][4];

    // =================== PHASE 1: z = X @ Wc ===================
#pragma unroll
    for (int i = 0; i < 2; i++)
#pragma unroll
        for (int j = 0; j < NF; j++)
#pragma unroll
            for (int k = 0; k < 4; k++) c[i][j][k] = 0.f;

#pragma unroll
    for (int split = 0; split < 3; split++) {
        const uint32_t aB = (split == 2) ? uAl : uAh;
        const uint32_t bB = (split == 1) ? uBl : uBh;
#pragma unroll
        for (int ks = 0; ks < 8; ks++) {
            uint32_t a[2][4];
#pragma unroll
            for (int i = 0; i < 2; i++)
                ldmx4(a[i], aB + (uint32_t)(((arow + i * 16) * LDA + ks * 16 + acol8) * 2));
            uint32_t b[NF][2];
#pragma unroll
            for (int j = 0; j < NF; j++)
                ldmx2(b[j], bB + (uint32_t)(((brow + j * 8) * LDA + ks * 16 + bcol8) * 2));
#pragma unroll
            for (int i = 0; i < 2; i++)
#pragma unroll
                for (int j = 0; j < NF; j++) mma16816(c[i][j], a[i], b[j]);
        }
    }
    __syncthreads();   // phase-1 reads of sB done

    // ---- fill B = Wl (hoisted: LDG latency hidden under epilogue below) ----
    for (int idx = tid; idx < N * 16; idx += 256) {
        int r = idx >> 4, cc = idx & 15;
        *(uint4*)&sBh[r * LDA + cc * 8] = *(const uint4*)&Bl_hi[r * 128 + cc * 8];
        *(uint4*)&sBl[r * LDA + cc * 8] = *(const uint4*)&Bl_lo[r * 128 + cc * 8];
    }

    // ---- epilogue 1: store z + el/er from accumulators (no sB use) ----
    float elp[4][2], erp[4][2];
#pragma unroll
    for (int s = 0; s < 4; s++) { elp[s][0] = elp[s][1] = erp[s][0] = erp[s][1] = 0.f; }
#pragma unroll
    for (int i = 0; i < 2; i++) {
#pragma unroll
        for (int half = 0; half < 2; half++) {
            int r = row0 + wm * 32 + i * 16 + quad + half * 8;
            if (r < n) {
#pragma unroll
                for (int j = 0; j < NF; j++) {
                    int col = wn * (N / 2) + j * 8 + tq * 2;
                    float v0 = c[i][j][half * 2], v1 = c[i][j][half * 2 + 1];
                    *(float2*)&z[r * N + col] = make_float2(v0, v1);
                    int hloc = (j * 8) / FOUT;
                    elp[i * 2 + half][hloc] += v0 * __ldg(&al[col]) + v1 * __ldg(&al[col + 1]);
                    erp[i * 2 + half][hloc] += v0 * __ldg(&ar[col]) + v1 * __ldg(&ar[col + 1]);
                }
            }
        }
    }
#pragma unroll
    for (int s = 0; s < 4; s++) {
#pragma unroll
        for (int h = 0; h < 2; h++) {
            float e = elp[s][h], f = erp[s][h];
            e += __shfl_xor_sync(0xFFFFFFFFu, e, 1);
            e += __shfl_xor_sync(0xFFFFFFFFu, e, 2);
            f += __shfl_xor_sync(0xFFFFFFFFu, f, 1);
            f += __shfl_xor_sync(0xFFFFFFFFu, f, 2);
            if (tq == 0) {
                int i = s >> 1, half = s & 1;
                int r = row0 + wm * 32 + i * 16 + quad + half * 8;
                if (r < n) {
                    int hg = wn * 2 + h;
                    el[r * 4 + hg] = e;
                    er[r * 4 + hg] = f;
                }
            }
        }
    }
    __syncthreads();   // Wl fill complete + epilogue done

    // =================== PHASE 2: out = X @ Wl + bc ===================
#pragma unroll
    for (int i = 0; i < 2; i++)
#pragma unroll
        for (int j = 0; j < NF; j++)
#pragma unroll
            for (int k = 0; k < 4; k++) c[i][j][k] = 0.f;

#pragma unroll
    for (int split = 0; split < 3; split++) {
        const uint32_t aB = (split == 2) ? uAl : uAh;
        const uint32_t bB = (split == 1) ? uBl : uBh;
#pragma unroll
        for (int ks = 0; ks < 8; ks++) {
            uint32_t a[2][4];
#pragma unroll
            for (int i = 0; i < 2; i++)
                ldmx4(a[i], aB + (uint32_t)(((arow + i * 16) * LDA + ks * 16 + acol8) * 2));
            uint32_t b[NF][2];
#pragma unroll
            for (int j = 0; j < NF; j++)
                ldmx2(b[j], bB + (uint32_t)(((brow + j * 8) * LDA + ks * 16 + bcol8) * 2));
#pragma unroll
            for (int i = 0; i < 2; i++)
#pragma unroll
                for (int j = 0; j < NF; j++) mma16816(c[i][j], a[i], b[j]);
        }
    }

#pragma unroll
    for (int i = 0; i < 2; i++) {
#pragma unroll
        for (int half = 0; half < 2; half++) {
            int r = row0 + wm * 32 + i * 16 + quad + half * 8;
            if (r < n) {
#pragma unroll
                for (int j = 0; j < NF; j++) {
                    int col = wn * (N / 2) + j * 8 + tq * 2;
                    float2 v = make_float2(c[i][j][half * 2] + __ldg(&bcbias[col]),
                                           c[i][j][half * 2 + 1] + __ldg(&bcbias[col + 1]));
                    *(float2*)&out[r * N + col] = v;
                }
            }
        }
    }
}

// ================= CSR build =================
__global__ void count_kernel(const int* __restrict__ dst, int* __restrict__ deg, int E) {
    int e = blockIdx.x * blockDim.x + threadIdx.x;
    if (e < E) atomicAdd(&deg[dst[e]], 1);
}
__global__ void scan_partial(const int* __restrict__ deg, int* __restrict__ rowptr,
                             int* __restrict__ bsum, int n) {
    __shared__ int sdata[1024];
    int tid = threadIdx.x;
    int i = blockIdx.x * 1024 + tid;
    int v = (i < n) ? deg[i] : 0;
    sdata[tid] = v;
    __syncthreads();
    for (int off = 1; off < 1024; off <<= 1) {
        int t = (tid >= off) ? sdata[tid - off] : 0;
        __syncthreads();
        sdata[tid] += t;
        __syncthreads();
    }
    if (i < n) rowptr[i] = sdata[tid] - v;
    if (tid == 1023) bsum[blockIdx.x] = sdata[1023];
}
__global__ void scan_add(int* __restrict__ rowptr, const int* __restrict__ bsum,
                         int* __restrict__ wcur, int n, int nb) {
    __shared__ int s_pref, s_total;
    int t = threadIdx.x;
    if (t == 0) {
        int p = 0, tot = 0;
        for (int j = 0; j < nb; j++) {
            int v = bsum[j];
            if (j < (int)blockIdx.x) p += v;
            tot += v;
        }
        s_pref = p;
        s_total = tot;
    }
    __syncthreads();
    int i = blockIdx.x * 1024 + t;
    if (i < n) {
        int v = rowptr[i] + s_pref;
        rowptr[i] = v;
        wcur[i] = v;
    }
    if (i == 0) rowptr[n] = s_total;
}
__global__ void scatter_kernel(const int* __restrict__ src, const int* __restrict__ dst,
                               int* __restrict__ wcur, int* __restrict__ csrsrc, int E) {
    int e = blockIdx.x * blockDim.x + threadIdx.x;
    if (e < E) {
        int pos = atomicAdd(&wcur[dst[e]], 1);
        csrsrc[pos] = src[e];
    }
}

// ================= online-softmax helpers =================
#define OSM_STEP(m, l, e)                                  \
    do {                                                   \
        float _nm = fmaxf(m, e);                           \
        l = l * __expf(m - _nm) + __expf(e - _nm);         \
        m = _nm;                                           \
    } while (0)
#define OSM_MERGE(m, l, om, ol)                            \
    do {                                                   \
        float _nm = fmaxf(m, om);                          \
        l = l * __expf(m - _nm) + ol * __expf(om - _nm);   \
        m = _nm;                                           \
    } while (0)

// ================= node_agg (layers 0/1): KOUT=128 + fused BN stats =========
// stats pass caches raw e-values in s_ex for i<CAP (avg deg=16 << CAP).
__global__ void node_agg_kernel(const int* __restrict__ rowptr, const int* __restrict__ csrsrc,
                                const float* __restrict__ el, const float* __restrict__ er,
                                const float* __restrict__ z, float* __restrict__ out,
                                float* __restrict__ bnsum, int n) {
    constexpr int WARPS = 8;
    constexpr int CAP = 64;
    __shared__ __align__(16) float4 s_ex[WARPS][CAP];
    __shared__ float sred[256];

    int tid = threadIdx.x;
    int wid = tid >> 5;
    int lane = tid & 31;
    int node = blockIdx.x * WARPS + wid;

    if (tid < 256) sred[tid] = 0.f;
    __syncthreads();

    bool active = node < n;
    int beg = 0, deg = 0;
    if (active) {
        beg = rowptr[node];
        deg = rowptr[node + 1] - beg;
    }

    float4 acc = make_float4(0.f, 0.f, 0.f, 0.f);
    if (active && deg > 0) {
        float4 erv = *(const float4*)&er[node * 4];
        float m0 = NEG_INF, m1 = NEG_INF, m2 = NEG_INF, m3 = NEG_INF;
        float l0 = 0.f, l1 = 0.f, l2 = 0.f, l3 = 0.f;
        for (int i = lane; i < deg; i += 32) {
            int s = __ldg(&csrsrc[beg + i]);
            float4 a = __ldg((const float4*)&el[s * 4]);
            float4 e;
            e.x = lrelu(a.x + erv.x);
            e.y = lrelu(a.y + erv.y);
            e.z = lrelu(a.z + erv.z);
            e.w = lrelu(a.w + erv.w);
            if (i < CAP) s_ex[wid][i] = e;   // cache raw e-values
            OSM_STEP(m0, l0, e.x);
            OSM_STEP(m1, l1, e.y);
            OSM_STEP(m2, l2, e.z);
            OSM_STEP(m3, l3, e.w);
        }
#pragma unroll
        for (int off = 16; off > 0; off >>= 1) {
            float om, ol;
            om = __shfl_xor_sync(0xFFFFFFFFu, m0, off); ol = __shfl_xor_sync(0xFFFFFFFFu, l0, off);
            OSM_MERGE(m0, l0, om, ol);
            om = __shfl_xor_sync(0xFFFFFFFFu, m1, off); ol = __shfl_xor_sync(0xFFFFFFFFu, l1, off);
            OSM_MERGE(m1, l1, om, ol);
            om = __shfl_xor_sync(0xFFFFFFFFu, m2, off); ol = __shfl_xor_sync(0xFFFFFFFFu, l2, off);
            OSM_MERGE(m2, l2, om, ol);
            om = __shfl_xor_sync(0xFFFFFFFFu, m3, off); ol = __shfl_xor_sync(0xFFFFFFFFu, l3, off);
            OSM_MERGE(m3, l3, om, ol);
        }
        float r0 = 1.f / l0, r1 = 1.f / l1, r2 = 1.f / l2, r3 = 1.f / l3;
        int h = lane >> 3;

        for (int base = 0; base < deg; base += CAP) {
            int cnt = min(CAP, deg - base);
            __syncwarp();
            for (int i = lane; i < cnt; i += 32) {
                float4 e;
                if (base == 0) {
                    e = s_ex[wid][i];                 // cached raw e
                } else {
                    int s = __ldg(&csrsrc[beg + base + i]);
                    float4 a = __ldg((const float4*)&el[s * 4]);
                    e.x = lrelu(a.x + erv.x);
                    e.y = lrelu(a.y + erv.y);
                    e.z = lrelu(a.z + erv.z);
                    e.w = lrelu(a.w + erv.w);
                }
                float4 ex;
                ex.x = __expf(e.x - m0) * r0;
                ex.y = __expf(e.y - m1) * r1;
                ex.z = __expf(e.z - m2) * r2;
                ex.w = __expf(e.w - m3) * r3;
                s_ex[wid][i] = ex;
            }
            __syncwarp();
#pragma unroll 2
            for (int i = 0; i < cnt; i++) {
                int s = __ldg(&csrsrc[beg + base + i]);
                float4 ex4 = s_ex[wid][i];
                float a = (h == 0) ? ex4.x : (h == 1) ? ex4.y : (h == 2) ? ex4.z : ex4.w;
                float4 zv = __ldg((const float4*)&z[s * 128 + lane * 4]);
                acc.x += a * zv.x;
                acc.y += a * zv.y;
                acc.z += a * zv.z;
                acc.w += a * zv.w;
            }
        }
    }

    float4 o = make_float4(0.f, 0.f, 0.f, 0.f);
    if (active) {
        o = *(float4*)&out[node * 128 + lane * 4];
        o.x += acc.x; o.y += acc.y; o.z += acc.z; o.w += acc.w;
        if (deg > 0) *(float4*)&out[node * 128 + lane * 4] = o;
    }

    if (active) {
        int c = lane * 4;
        atomicAdd(&sred[c + 0], o.x);
        atomicAdd(&sred[c + 1], o.y);
        atomicAdd(&sred[c + 2], o.z);
        atomicAdd(&sred[c + 3], o.w);
        atomicAdd(&sred[128 + c + 0], o.x * o.x);
        atomicAdd(&sred[128 + c + 1], o.y * o.y);
        atomicAdd(&sred[128 + c + 2], o.z * o.z);
        atomicAdd(&sred[128 + c + 3], o.w * o.w);
    }
    __syncthreads();
    if (tid < 128) {
        atomicAdd(&bnsum[tid], sred[tid]);
        atomicAdd(&bnsum[128 + tid], sred[128 + tid]);
    }
}

// ================= node_agg_final (layer 2): KOUT=160 + head-mean -> d_out ===
__global__ void node_agg_final(const int* __restrict__ rowptr, const int* __restrict__ csrsrc,
                               const float* __restrict__ el, const float* __restrict__ er,
                               const float* __restrict__ z, const float* __restrict__ lin,
                               const float* __restrict__ bias_last, float* __restrict__ outF,
                               int n) {
    constexpr int WARPS = 8;
    constexpr int CAP = 64;
    __shared__ __align__(16) float4 s_ex[WARPS][CAP];

    int wid = threadIdx.x >> 5;
    int lane = threadIdx.x & 31;
    int node = blockIdx.x * WARPS + wid;
    if (node >= n) return;
    int beg = rowptr[node];
    int deg = rowptr[node + 1] - beg;

    float4 acc0 = make_float4(0.f, 0.f, 0.f, 0.f);
    float4 acc1 = make_float4(0.f, 0.f, 0.f, 0.f);

    if (deg > 0) {
        float4 erv = *(const float4*)&er[node * 4];
        float m0 = NEG_INF, m1 = NEG_INF, m2 = NEG_INF, m3 = NEG_INF;
        float l0 = 0.f, l1 = 0.f, l2 = 0.f, l3 = 0.f;
        for (int i = lane; i < deg; i += 32) {
            int s = __ldg(&csrsrc[beg + i]);
            float4 a = __ldg((const float4*)&el[s * 4]);
            float4 e;
            e.x = lrelu(a.x + erv.x);
            e.y = lrelu(a.y + erv.y);
            e.z = lrelu(a.z + erv.z);
            e.w = lrelu(a.w + erv.w);
            if (i < CAP) s_ex[wid][i] = e;
            OSM_STEP(m0, l0, e.x);
            OSM_STEP(m1, l1, e.y);
            OSM_STEP(m2, l2, e.z);
            OSM_STEP(m3, l3, e.w);
        }
#pragma unroll
        for (int off = 16; off > 0; off >>= 1) {
            float om, ol;
            om = __shfl_xor_sync(0xFFFFFFFFu, m0, off); ol = __shfl_xor_sync(0xFFFFFFFFu, l0, off);
            OSM_MERGE(m0, l0, om, ol);
            om = __shfl_xor_sync(0xFFFFFFFFu, m1, off); ol = __shfl_xor_sync(0xFFFFFFFFu, l1, off);
            OSM_MERGE(m1, l1, om, ol);
            om = __shfl_xor_sync(0xFFFFFFFFu, m2, off); ol = __shfl_xor_sync(0xFFFFFFFFu, l2, off);
            OSM_MERGE(m2, l2, om, ol);
            om = __shfl_xor_sync(0xFFFFFFFFu, m3, off); ol = __shfl_xor_sync(0xFFFFFFFFu, l3, off);
            OSM_MERGE(m3, l3, om, ol);
        }
        float r0 = 1.f / l0, r1 = 1.f / l1, r2 = 1.f / l2, r3 = 1.f / l3;

        int h0 = (lane * 4) / 40;
        int h1 = ((lane + 32) * 4) / 40;

        for (int base = 0; base < deg; base += CAP) {
            int cnt = min(CAP, deg - base);
            __syncwarp();
            for (int i = lane; i < cnt; i += 32) {
                float4 e;
                if (base == 0) {
                    e = s_ex[wid][i];
                } else {
                    int s = __ldg(&csrsrc[beg + base + i]);
                    float4 a = __ldg((const float4*)&el[s * 4]);
                    e.x = lrelu(a.x + erv.x);
                    e.y = lrelu(a.y + erv.y);
                    e.z = lrelu(a.z + erv.z);
                    e.w = lrelu(a.w + erv.w);
                }
                float4 ex;
                ex.x = __expf(e.x - m0) * r0;
                ex.y = __expf(e.y - m1) * r1;
                ex.z = __expf(e.z - m2) * r2;
                ex.w = __expf(e.w - m3) * r3;
                s_ex[wid][i] = ex;
            }
            __syncwarp();
#pragma unroll 2
            for (int i = 0; i < cnt; i++) {
                int s = __ldg(&csrsrc[beg + base + i]);
                float4 ex4 = s_ex[wid][i];
                float a0 = (h0 == 0) ? ex4.x : (h0 == 1) ? ex4.y : (h0 == 2) ? ex4.z : ex4.w;
                float4 zv = __ldg((const float4*)&z[s * 160 + lane * 4]);
                acc0.x += a0 * zv.x;
                acc0.y += a0 * zv.y;
                acc0.z += a0 * zv.z;
                acc0.w += a0 * zv.w;
                if (lane < 8) {
                    float a1 = (h1 == 3) ? ex4.w : ex4.z;
                    float4 zw = __ldg((const float4*)&z[s * 160 + 128 + lane * 4]);
                    acc1.x += a1 * zw.x;
                    acc1.y += a1 * zw.y;
                    acc1.z += a1 * zw.z;
                    acc1.w += a1 * zw.w;
                }
            }
        }
    }

    float4 o0 = *(const float4*)&lin[node * 160 + lane * 4];
    o0.x += acc0.x; o0.y += acc0.y; o0.z += acc0.z; o0.w += acc0.w;
    float4 o1 = make_float4(0.f, 0.f, 0.f, 0.f);
    if (lane < 8) {
        o1 = *(const float4*)&lin[node * 160 + 128 + lane * 4];
        o1.x += acc1.x; o1.y += acc1.y; o1.z += acc1.z; o1.w += acc1.w;
    }

    int i1 = lane + 10, i2 = lane + 20, i3a = lane + 30, i3b = (lane - 2) & 31;
    float4 v1, v2, v3a, v3b;
    v1.x = __shfl_sync(0xFFFFFFFFu, o0.x, i1); v1.y = __shfl_sync(0xFFFFFFFFu, o0.y, i1);
    v1.z = __shfl_sync(0xFFFFFFFFu, o0.z, i1); v1.w = __shfl_sync(0xFFFFFFFFu, o0.w, i1);
    v2.x = __shfl_sync(0xFFFFFFFFu, o0.x, i2); v2.y = __shfl_sync(0xFFFFFFFFu, o0.y, i2);
    v2.z = __shfl_sync(0xFFFFFFFFu, o0.z, i2); v2.w = __shfl_sync(0xFFFFFFFFu, o0.w, i2);
    v3a.x = __shfl_sync(0xFFFFFFFFu, o0.x, i3a); v3a.y = __shfl_sync(0xFFFFFFFFu, o0.y, i3a);
    v3a.z = __shfl_sync(0xFFFFFFFFu, o0.z, i3a); v3a.w = __shfl_sync(0xFFFFFFFFu, o0.w, i3a);
    v3b.x = __shfl_sync(0xFFFFFFFFu, o1.x, i3b); v3b.y = __shfl_sync(0xFFFFFFFFu, o1.y, i3b);
    v3b.z = __shfl_sync(0xFFFFFFFFu, o1.z, i3b); v3b.w = __shfl_sync(0xFFFFFFFFu, o1.w, i3b);
    if (lane < 10) {
        float4 v3 = (lane < 2) ? v3a : v3b;
        float4 bl = *(const float4*)&bias_last[lane * 4];
        float4 r;
        r.x = 0.25f * (o0.x + v1.x + v2.x + v3.x) + bl.x;
        r.y = 0.25f * (o0.y + v1.y + v2.y + v3.y) + bl.y;
        r.z = 0.25f * (o0.z + v1.z + v2.z + v3.z) + bl.z;
        r.w = 0.25f * (o0.w + v1.w + v2.w + v3.w) + bl.w;
        *(float4*)&outF[node * 40 + lane * 4] = r;
    }
}

// ---------------------------------------------------------------------------
extern "C" void kernel_launch(void* const* d_in, const int* in_sizes, int n_in,
                              void* d_out, int out_size) {
    const float* feat = (const float*)d_in[0];
    const int* src = (const int*)d_in[1];
    const int* dst = (const int*)d_in[2];
    const float* Wc[3] = {(const float*)d_in[3], (const float*)d_in[8], (const float*)d_in[13]};
    const float* al[3] = {(const float*)d_in[4], (const float*)d_in[9], (const float*)d_in[14]};
    const float* ar[3] = {(const float*)d_in[5], (const float*)d_in[10], (const float*)d_in[15]};
    const float* bc[3] = {(const float*)d_in[6], (const float*)d_in[11], (const float*)d_in[16]};
    const float* Wl[3] = {(const float*)d_in[7], (const float*)d_in[12], (const float*)d_in[17]};
    const float* g0 = (const float*)d_in[18];
    const float* b0 = (const float*)d_in[19];
    const float* g1 = (const float*)d_in[20];
    const float* b1 = (const float*)d_in[21];
    const float* bias_last = (const float*)d_in[22];

    const int n = in_sizes[0] / 128;  // 50000
    const int E = in_sizes[1];        // 800000

    float *z, *bufA, *bufB, *el, *er, *bnA, *bnB;
    int *deg, *rowptr, *wcur, *csrsrc, *bsum;
    __nv_bfloat16 *wthi, *wtlo;
    cudaGetSymbolAddress((void**)&z, g_z);
    cudaGetSymbolAddress((void**)&bufA, g_bufA);
    cudaGetSymbolAddress((void**)&bufB, g_bufB);
    cudaGetSymbolAddress((void**)&el, g_el);
    cudaGetSymbolAddress((void**)&er, g_er);
    cudaGetSymbolAddress((void**)&bnA, g_bnsumA);
    cudaGetSymbolAddress((void**)&bnB, g_bnsumB);
    cudaGetSymbolAddress((void**)&deg, g_deg);
    cudaGetSymbolAddress((void**)&rowptr, g_rowptr);
    cudaGetSymbolAddress((void**)&wcur, g_wcur);
    cudaGetSymbolAddress((void**)&csrsrc, g_csrsrc);
    cudaGetSymbolAddress((void**)&bsum, g_bsum);
    cudaGetSymbolAddress((void**)&wthi, g_wthi);
    cudaGetSymbolAddress((void**)&wtlo, g_wtlo);

    const int edge_blocks = (E + 255) / 256;
    const int agg_blocks = (n + 7) / 8;
    const int gemm_grid = (n + 127) / 128;
    const int nb = (n + 1023) / 1024;

    const int smem128 = (256 + 256) * 136 * 2;  // 139264
    const int smem160 = (256 + 320) * 136 * 2;  // 156672
    cudaFuncSetAttribute(gemm_dual<128, 32, false>, cudaFuncAttributeMaxDynamicSharedMemorySize, smem128);
    cudaFuncSetAttribute(gemm_dual<128, 32, true>, cudaFuncAttributeMaxDynamicSharedMemorySize, smem128);
    cudaFuncSetAttribute(gemm_dual<160, 40, true>, cudaFuncAttributeMaxDynamicSharedMemorySize, smem160);

    wsplit_all<<<(106496 + 255) / 256, 256>>>(Wc[0], Wl[0], Wc[1], Wl[1], Wc[2], Wl[2],
                                              wthi, wtlo, deg, bnA, bnB, n);
    count_kernel<<<edge_blocks, 256>>>(dst, deg, E);
    scan_partial<<<nb, 1024>>>(deg, rowptr, bsum, n);
    scan_add<<<nb, 1024>>>(rowptr, bsum, wcur, n, nb);

    gemm_dual<128, 32, false><<<gemm_grid, 256, smem128>>>(
        feat, wthi + 0 * WS, wtlo + 0 * WS, wthi + 1 * WS, wtlo + 1 * WS, bc[0],
        nullptr, nullptr, nullptr, z, bufA, al[0], ar[0], el, er, n);

    scatter_kernel<<<edge_blocks, 256>>>(src, dst, wcur, csrsrc, E);

    node_agg_kernel<<<agg_blocks, 256>>>(rowptr, csrsrc, el, er, z, bufA, bnA, n);

    gemm_dual<128, 32, true><<<gemm_grid, 256, smem128>>>(
        bufA, wthi + 2 * WS, wtlo + 2 * WS, wthi + 3 * WS, wtlo + 3 * WS, bc[1],
        bnA, g0, b0, z, bufB, al[1], ar[1], el, er, n);
    node_agg_kernel<<<agg_blocks, 256>>>(rowptr, csrsrc, el, er, z, bufB, bnB, n);

    gemm_dual<160, 40, true><<<gemm_grid, 256, smem160>>>(
        bufB, wthi + 4 * WS, wtlo + 4 * WS, wthi + 5 * WS, wtlo + 5 * WS, bc[2],
        bnB, g1, b1, z, bufA, al[2], ar[2], el, er, n);
    node_agg_final<<<agg_blocks, 256>>>(rowptr, csrsrc, el, er, z, bufA, bias_last,
                                        (float*)d_out, n);
}

// round 14
// speedup vs baseline: 1.0397x; 1.0397x over previous
#include <cuda_runtime.h>
#include <cuda_bf16.h>
#include <cstdint>

// ---------------------------------------------------------------------------
// GAT R13: R11 core (527us) + paired ldmatrix.x4 B-loads in gemm mainloop +
// parallel prefix in scan_add. R12's e-caching/hoist reverted (regressed).
// ---------------------------------------------------------------------------

#define NMAX 50000
#define EMAX 800000
#define SLOPE 0.2f
#define BN_EPS 1e-5f
#define NEG_INF (-1e30f)
#define WS (160 * 128)

// ---------------- scratch ----------------
__device__ __align__(16) float g_z  [NMAX * 160];
__device__ __align__(16) float g_bufA[NMAX * 160];
__device__ __align__(16) float g_bufB[NMAX * 128];
__device__ __align__(16) float g_el [NMAX * 4];
__device__ __align__(16) float g_er [NMAX * 4];
__device__ __align__(16) float g_bnsumA[256];
__device__ __align__(16) float g_bnsumB[256];
__device__ int g_deg[NMAX];
__device__ int g_rowptr[NMAX + 1];
__device__ int g_wcur[NMAX];
__device__ int g_csrsrc[EMAX];
__device__ int g_bsum[64];
__device__ __align__(16) __nv_bfloat16 g_wthi[6][WS];
__device__ __align__(16) __nv_bfloat16 g_wtlo[6][WS];

__device__ __forceinline__ uint32_t smem_u32(const void* p) {
    uint32_t a;
    asm("{ .reg .u64 t; cvta.to.shared.u64 t, %1; cvt.u32.u64 %0, t; }" : "=r"(a) : "l"(p));
    return a;
}
__device__ __forceinline__ float lrelu(float x) { return x >= 0.f ? x : SLOPE * x; }

__device__ __forceinline__ void ldmx4(uint32_t* r, uint32_t addr) {
    asm volatile("ldmatrix.sync.aligned.m8n8.x4.shared.b16 {%0,%1,%2,%3}, [%4];"
                 : "=r"(r[0]), "=r"(r[1]), "=r"(r[2]), "=r"(r[3]) : "r"(addr));
}
__device__ __forceinline__ void mma16816(float* c, const uint32_t* a, const uint32_t* b) {
    asm volatile(
        "mma.sync.aligned.m16n8k16.row.col.f32.bf16.bf16.f32 "
        "{%0,%1,%2,%3}, {%4,%5,%6,%7}, {%8,%9}, {%0,%1,%2,%3};"
        : "+f"(c[0]), "+f"(c[1]), "+f"(c[2]), "+f"(c[3])
        : "r"(a[0]), "r"(a[1]), "r"(a[2]), "r"(a[3]), "r"(b[0]), "r"(b[1]));
}

// ================= wsplit_all: 6 weight matrices + zero deg/bnsum ===========
__global__ void wsplit_all(const float* __restrict__ W0, const float* __restrict__ W1,
                           const float* __restrict__ W2, const float* __restrict__ W3,
                           const float* __restrict__ W4, const float* __restrict__ W5,
                           __nv_bfloat16* __restrict__ hi, __nv_bfloat16* __restrict__ lo,
                           int* __restrict__ deg, float* __restrict__ bnA,
                           float* __restrict__ bnB, int n) {
    int i = blockIdx.x * blockDim.x + threadIdx.x;
    if (i < n) deg[i] = 0;
    if (i < 256) { bnA[i] = 0.f; bnB[i] = 0.f; }
    if (i < 106496) {
        int m, base, N;
        if (i < 65536)      { m = i >> 14; base = m << 14; N = 128; }
        else if (i < 86016) { m = 4; base = 65536; N = 160; }
        else                { m = 5; base = 86016; N = 160; }
        int k = i - base;
        int nn = k >> 7, kk = k & 127;
        const float* W = (m == 0) ? W0 : (m == 1) ? W1 : (m == 2) ? W2
                       : (m == 3) ? W3 : (m == 4) ? W4 : W5;
        float v = W[kk * N + nn];
        __nv_bfloat16 h = __float2bfloat16(v);
        hi[m * WS + k] = h;
        lo[m * WS + k] = __float2bfloat16(v - __bfloat162float(h));
    }
}

// ================= dual GEMM (paired x4 B-loads) =================
template <int N, int FOUT, bool BNIN>
__global__ void __launch_bounds__(256, 1)
gemm_dual(const float* __restrict__ X,
          const __nv_bfloat16* __restrict__ Bc_hi, const __nv_bfloat16* __restrict__ Bc_lo,
          const __nv_bfloat16* __restrict__ Bl_hi, const __nv_bfloat16* __restrict__ Bl_lo,
          const float* __restrict__ bcbias,
          const float* __restrict__ bnsum, const float* __restrict__ bng,
          const float* __restrict__ bnb,
          float* __restrict__ z, float* __restrict__ out,
          const float* __restrict__ al, const float* __restrict__ ar,
          float* __restrict__ el, float* __restrict__ er, int n) {
    constexpr int LDA = 136;
    constexpr int NF = N / 16;
    extern __shared__ __align__(16) char smem[];
    __nv_bfloat16* sAh = (__nv_bfloat16*)smem;
    __nv_bfloat16* sAl = sAh + 128 * LDA;
    __nv_bfloat16* sBh = sAl + 128 * LDA;
    __nv_bfloat16* sBl = sBh + N * LDA;
    __shared__ float s_bn[256];

    const int tid = threadIdx.x;
    const int wid = tid >> 5;
    const int lane = tid & 31;
    const int wm = wid & 3;
    const int wn = wid >> 2;
    const int quad = lane >> 2, tq = lane & 3;
    const int row0 = blockIdx.x * 128;

    if (BNIN) {
        if (tid < 128) {
            float inv_n = 1.f / (float)n;
            float mean = bnsum[tid] * inv_n;
            float var = bnsum[128 + tid] * inv_n - mean * mean;
            float s = bng[tid] * rsqrtf(var + BN_EPS);
            s_bn[tid] = s;
            s_bn[128 + tid] = bnb[tid] - mean * s;
        }
        __syncthreads();
    }

    // ---- fill A ----
    for (int idx = tid; idx < 128 * 32; idx += 256) {
        int r = idx >> 5, c4 = idx & 31;
        int gr = row0 + r;
        float4 v = make_float4(0.f, 0.f, 0.f, 0.f);
        if (gr < n) {
            v = *(const float4*)&X[gr * 128 + c4 * 4];
            if (BNIN) {
                int c = c4 * 4;
                v.x = fmaxf(0.f, fmaf(v.x, s_bn[c + 0], s_bn[128 + c + 0]));
                v.y = fmaxf(0.f, fmaf(v.y, s_bn[c + 1], s_bn[128 + c + 1]));
                v.z = fmaxf(0.f, fmaf(v.z, s_bn[c + 2], s_bn[128 + c + 2]));
                v.w = fmaxf(0.f, fmaf(v.w, s_bn[c + 3], s_bn[128 + c + 3]));
            }
        }
        __nv_bfloat162 h01, h23, l01, l23;
        h01.x = __float2bfloat16(v.x); l01.x = __float2bfloat16(v.x - __bfloat162float(h01.x));
        h01.y = __float2bfloat16(v.y); l01.y = __float2bfloat16(v.y - __bfloat162float(h01.y));
        h23.x = __float2bfloat16(v.z); l23.x = __float2bfloat16(v.z - __bfloat162float(h23.x));
        h23.y = __float2bfloat16(v.w); l23.y = __float2bfloat16(v.w - __bfloat162float(h23.y));
        uint2 hu, lu;
        hu.x = *(uint32_t*)&h01; hu.y = *(uint32_t*)&h23;
        lu.x = *(uint32_t*)&l01; lu.y = *(uint32_t*)&l23;
        *(uint2*)&sAh[r * LDA + c4 * 4] = hu;
        *(uint2*)&sAl[r * LDA + c4 * 4] = lu;
    }
    // ---- fill B = Wc ----
    for (int idx = tid; idx < N * 16; idx += 256) {
        int r = idx >> 4, c = idx & 15;
        *(uint4*)&sBh[r * LDA + c * 8] = *(const uint4*)&Bc_hi[r * 128 + c * 8];
        *(uint4*)&sBl[r * LDA + c * 8] = *(const uint4*)&Bc_lo[r * 128 + c * 8];
    }
    __syncthreads();

    const uint32_t uAh = smem_u32(sAh), uAl = smem_u32(sAl);
    const uint32_t uBh = smem_u32(sBh), uBl = smem_u32(sBl);
    const int arow = wm * 32 + (lane & 15);
    const int acol8 = (lane >> 4) * 8;
    // paired-x4 B addressing: lanes 0-7 -> block j half0, 8-15 -> j half1,
    // 16-23 -> block j+1 half0, 24-31 -> j+1 half1.
    const int browx = wn * (N / 2) + (lane & 7) + ((lane >> 4) & 1) * 8;
    const int bcol8 = ((lane >> 3) & 1) * 8;

    float c[2][NF][4];

#define RUN_MAINLOOP()                                                                    \
    _Pragma("unroll")                                                                     \
    for (int split = 0; split < 3; split++) {                                             \
        const uint32_t aB = (split == 2) ? uAl : uAh;                                     \
        const uint32_t bB = (split == 1) ? uBl : uBh;                                     \
        _Pragma("unroll")                                                                 \
        for (int ks = 0; ks < 8; ks++) {                                                  \
            uint32_t a[2][4];                                                             \
            _Pragma("unroll")                                                             \
            for (int i = 0; i < 2; i++)                                                   \
                ldmx4(a[i], aB + (uint32_t)(((arow + i * 16) * LDA + ks * 16 + acol8) * 2)); \
            uint32_t b[NF][2];                                                            \
            _Pragma("unroll")                                                             \
            for (int j = 0; j < NF; j += 2) {                                             \
                uint32_t r4[4];                                                           \
                ldmx4(r4, bB + (uint32_t)(((browx + j * 8) * LDA + ks * 16 + bcol8) * 2)); \
                b[j][0] = r4[0]; b[j][1] = r4[1];                                         \
                b[j + 1][0] = r4[2]; b[j + 1][1] = r4[3];                                 \
            }                                                                             \
            _Pragma("unroll")                                                             \
            for (int i = 0; i < 2; i++)                                                   \
                _Pragma("unroll")                                                         \
                for (int j = 0; j < NF; j++) mma16816(c[i][j], a[i], b[j]);               \
        }                                                                                 \
    }

    // =================== PHASE 1: z = X @ Wc ===================
#pragma unroll
    for (int i = 0; i < 2; i++)
#pragma unroll
        for (int j = 0; j < NF; j++)
#pragma unroll
            for (int k = 0; k < 4; k++) c[i][j][k] = 0.f;

    RUN_MAINLOOP()

    // store z + el/er from accumulators
    float elp[4][2], erp[4][2];
#pragma unroll
    for (int s = 0; s < 4; s++) { elp[s][0] = elp[s][1] = erp[s][0] = erp[s][1] = 0.f; }
#pragma unroll
    for (int i = 0; i < 2; i++) {
#pragma unroll
        for (int half = 0; half < 2; half++) {
            int r = row0 + wm * 32 + i * 16 + quad + half * 8;
            if (r < n) {
#pragma unroll
                for (int j = 0; j < NF; j++) {
                    int col = wn * (N / 2) + j * 8 + tq * 2;
                    float v0 = c[i][j][half * 2], v1 = c[i][j][half * 2 + 1];
                    *(float2*)&z[r * N + col] = make_float2(v0, v1);
                    int hloc = (j * 8) / FOUT;
                    elp[i * 2 + half][hloc] += v0 * __ldg(&al[col]) + v1 * __ldg(&al[col + 1]);
                    erp[i * 2 + half][hloc] += v0 * __ldg(&ar[col]) + v1 * __ldg(&ar[col + 1]);
                }
            }
        }
    }
#pragma unroll
    for (int s = 0; s < 4; s++) {
#pragma unroll
        for (int h = 0; h < 2; h++) {
            float e = elp[s][h], f = erp[s][h];
            e += __shfl_xor_sync(0xFFFFFFFFu, e, 1);
            e += __shfl_xor_sync(0xFFFFFFFFu, e, 2);
            f += __shfl_xor_sync(0xFFFFFFFFu, f, 1);
            f += __shfl_xor_sync(0xFFFFFFFFu, f, 2);
            if (tq == 0) {
                int i = s >> 1, half = s & 1;
                int r = row0 + wm * 32 + i * 16 + quad + half * 8;
                if (r < n) {
                    int hg = wn * 2 + h;
                    el[r * 4 + hg] = e;
                    er[r * 4 + hg] = f;
                }
            }
        }
    }
    __syncthreads();

    // ---- fill B = Wl ----
    for (int idx = tid; idx < N * 16; idx += 256) {
        int r = idx >> 4, cc = idx & 15;
        *(uint4*)&sBh[r * LDA + cc * 8] = *(const uint4*)&Bl_hi[r * 128 + cc * 8];
        *(uint4*)&sBl[r * LDA + cc * 8] = *(const uint4*)&Bl_lo[r * 128 + cc * 8];
    }
    __syncthreads();

    // =================== PHASE 2: out = X @ Wl + bc ===================
#pragma unroll
    for (int i = 0; i < 2; i++)
#pragma unroll
        for (int j = 0; j < NF; j++)
#pragma unroll
            for (int k = 0; k < 4; k++) c[i][j][k] = 0.f;

    RUN_MAINLOOP()

#pragma unroll
    for (int i = 0; i < 2; i++) {
#pragma unroll
        for (int half = 0; half < 2; half++) {
            int r = row0 + wm * 32 + i * 16 + quad + half * 8;
            if (r < n) {
#pragma unroll
                for (int j = 0; j < NF; j++) {
                    int col = wn * (N / 2) + j * 8 + tq * 2;
                    float2 v = make_float2(c[i][j][half * 2] + __ldg(&bcbias[col]),
                                           c[i][j][half * 2 + 1] + __ldg(&bcbias[col + 1]));
                    *(float2*)&out[r * N + col] = v;
                }
            }
        }
    }
#undef RUN_MAINLOOP
}

// ================= CSR build =================
__global__ void count_kernel(const int* __restrict__ dst, int* __restrict__ deg, int E) {
    int e = blockIdx.x * blockDim.x + threadIdx.x;
    if (e < E) atomicAdd(&deg[dst[e]], 1);
}
__global__ void scan_partial(const int* __restrict__ deg, int* __restrict__ rowptr,
                             int* __restrict__ bsum, int n) {
    __shared__ int sdata[1024];
    int tid = threadIdx.x;
    int i = blockIdx.x * 1024 + tid;
    int v = (i < n) ? deg[i] : 0;
    sdata[tid] = v;
    __syncthreads();
    for (int off = 1; off < 1024; off <<= 1) {
        int t = (tid >= off) ? sdata[tid - off] : 0;
        __syncthreads();
        sdata[tid] += t;
        __syncthreads();
    }
    if (i < n) rowptr[i] = sdata[tid] - v;
    if (tid == 1023) bsum[blockIdx.x] = sdata[1023];
}
// parallel 64-entry prefix over block sums (inclusive), all in smem.
__global__ void scan_add(int* __restrict__ rowptr, const int* __restrict__ bsum,
                         int* __restrict__ wcur, int n, int nb) {
    __shared__ int s_bs[64];
    int t = threadIdx.x;
    if (t < 64) s_bs[t] = (t < nb) ? bsum[t] : 0;
    __syncthreads();
    for (int off = 1; off < 64; off <<= 1) {
        int u = (t < 64 && t >= off) ? s_bs[t - off] : 0;
        __syncthreads();
        if (t < 64) s_bs[t] += u;
        __syncthreads();
    }
    int pref = (blockIdx.x == 0) ? 0 : s_bs[blockIdx.x - 1];
    int i = blockIdx.x * 1024 + t;
    if (i < n) {
        int v = rowptr[i] + pref;
        rowptr[i] = v;
        wcur[i] = v;
    }
    if (i == 0) rowptr[n] = s_bs[nb - 1];
}
__global__ void scatter_kernel(const int* __restrict__ src, const int* __restrict__ dst,
                               int* __restrict__ wcur, int* __restrict__ csrsrc, int E) {
    int e = blockIdx.x * blockDim.x + threadIdx.x;
    if (e < E) {
        int pos = atomicAdd(&wcur[dst[e]], 1);
        csrsrc[pos] = src[e];
    }
}

// ================= online-softmax helpers =================
#define OSM_STEP(m, l, e)                                  \
    do {                                                   \
        float _nm = fmaxf(m, e);                           \
        l = l * __expf(m - _nm) + __expf(e - _nm);         \
        m = _nm;                                           \
    } while (0)
#define OSM_MERGE(m, l, om, ol)                            \
    do {                                                   \
        float _nm = fmaxf(m, om);                          \
        l = l * __expf(m - _nm) + ol * __expf(om - _nm);   \
        m = _nm;                                           \
    } while (0)

// ================= node_agg (layers 0/1): KOUT=128 + fused BN stats =========
__global__ void node_agg_kernel(const int* __restrict__ rowptr, const int* __restrict__ csrsrc,
                                const float* __restrict__ el, const float* __restrict__ er,
                                const float* __restrict__ z, float* __restrict__ out,
                                float* __restrict__ bnsum, int n) {
    constexpr int WARPS = 8;
    constexpr int CAP = 64;
    __shared__ __align__(16) float4 s_ex[WARPS][CAP];
    __shared__ float sred[256];

    int tid = threadIdx.x;
    int wid = tid >> 5;
    int lane = tid & 31;
    int node = blockIdx.x * WARPS + wid;

    if (tid < 256) sred[tid] = 0.f;
    __syncthreads();

    bool active = node < n;
    int beg = 0, deg = 0;
    if (active) {
        beg = rowptr[node];
        deg = rowptr[node + 1] - beg;
    }

    float4 acc = make_float4(0.f, 0.f, 0.f, 0.f);
    if (active && deg > 0) {
        float4 erv = *(const float4*)&er[node * 4];
        float m0 = NEG_INF, m1 = NEG_INF, m2 = NEG_INF, m3 = NEG_INF;
        float l0 = 0.f, l1 = 0.f, l2 = 0.f, l3 = 0.f;
        for (int i = lane; i < deg; i += 32) {
            int s = __ldg(&csrsrc[beg + i]);
            float4 a = __ldg((const float4*)&el[s * 4]);
            OSM_STEP(m0, l0, lrelu(a.x + erv.x));
            OSM_STEP(m1, l1, lrelu(a.y + erv.y));
            OSM_STEP(m2, l2, lrelu(a.z + erv.z));
            OSM_STEP(m3, l3, lrelu(a.w + erv.w));
        }
#pragma unroll
        for (int off = 16; off > 0; off >>= 1) {
            float om, ol;
            om = __shfl_xor_sync(0xFFFFFFFFu, m0, off); ol = __shfl_xor_sync(0xFFFFFFFFu, l0, off);
            OSM_MERGE(m0, l0, om, ol);
            om = __shfl_xor_sync(0xFFFFFFFFu, m1, off); ol = __shfl_xor_sync(0xFFFFFFFFu, l1, off);
            OSM_MERGE(m1, l1, om, ol);
            om = __shfl_xor_sync(0xFFFFFFFFu, m2, off); ol = __shfl_xor_sync(0xFFFFFFFFu, l2, off);
            OSM_MERGE(m2, l2, om, ol);
            om = __shfl_xor_sync(0xFFFFFFFFu, m3, off); ol = __shfl_xor_sync(0xFFFFFFFFu, l3, off);
            OSM_MERGE(m3, l3, om, ol);
        }
        float r0 = 1.f / l0, r1 = 1.f / l1, r2 = 1.f / l2, r3 = 1.f / l3;
        int h = lane >> 3;

        for (int base = 0; base < deg; base += CAP) {
            int cnt = min(CAP, deg - base);
            for (int i = lane; i < cnt; i += 32) {
                int s = __ldg(&csrsrc[beg + base + i]);
                float4 a = __ldg((const float4*)&el[s * 4]);
                float4 ex;
                ex.x = __expf(lrelu(a.x + erv.x) - m0) * r0;
                ex.y = __expf(lrelu(a.y + erv.y) - m1) * r1;
                ex.z = __expf(lrelu(a.z + erv.z) - m2) * r2;
                ex.w = __expf(lrelu(a.w + erv.w) - m3) * r3;
                s_ex[wid][i] = ex;
            }
            __syncwarp();
#pragma unroll 2
            for (int i = 0; i < cnt; i++) {
                int s = __ldg(&csrsrc[beg + base + i]);
                float4 ex4 = s_ex[wid][i];
                float a = (h == 0) ? ex4.x : (h == 1) ? ex4.y : (h == 2) ? ex4.z : ex4.w;
                float4 zv = __ldg((const float4*)&z[s * 128 + lane * 4]);
                acc.x += a * zv.x;
                acc.y += a * zv.y;
                acc.z += a * zv.z;
                acc.w += a * zv.w;
            }
            __syncwarp();
        }
    }

    float4 o = make_float4(0.f, 0.f, 0.f, 0.f);
    if (active) {
        o = *(float4*)&out[node * 128 + lane * 4];
        o.x += acc.x; o.y += acc.y; o.z += acc.z; o.w += acc.w;
        if (deg > 0) *(float4*)&out[node * 128 + lane * 4] = o;
    }

    if (active) {
        int c = lane * 4;
        atomicAdd(&sred[c + 0], o.x);
        atomicAdd(&sred[c + 1], o.y);
        atomicAdd(&sred[c + 2], o.z);
        atomicAdd(&sred[c + 3], o.w);
        atomicAdd(&sred[128 + c + 0], o.x * o.x);
        atomicAdd(&sred[128 + c + 1], o.y * o.y);
        atomicAdd(&sred[128 + c + 2], o.z * o.z);
        atomicAdd(&sred[128 + c + 3], o.w * o.w);
    }
    __syncthreads();
    if (tid < 128) {
        atomicAdd(&bnsum[tid], sred[tid]);
        atomicAdd(&bnsum[128 + tid], sred[128 + tid]);
    }
}

// ================= node_agg_final (layer 2): KOUT=160 + head-mean -> d_out ===
__global__ void node_agg_final(const int* __restrict__ rowptr, const int* __restrict__ csrsrc,
                               const float* __restrict__ el, const float* __restrict__ er,
                               const float* __restrict__ z, const float* __restrict__ lin,
                               const float* __restrict__ bias_last, float* __restrict__ outF,
                               int n) {
    constexpr int WARPS = 8;
    constexpr int CAP = 64;
    __shared__ __align__(16) float4 s_ex[WARPS][CAP];

    int wid = threadIdx.x >> 5;
    int lane = threadIdx.x & 31;
    int node = blockIdx.x * WARPS + wid;
    if (node >= n) return;
    int beg = rowptr[node];
    int deg = rowptr[node + 1] - beg;

    float4 acc0 = make_float4(0.f, 0.f, 0.f, 0.f);
    float4 acc1 = make_float4(0.f, 0.f, 0.f, 0.f);

    if (deg > 0) {
        float4 erv = *(const float4*)&er[node * 4];
        float m0 = NEG_INF, m1 = NEG_INF, m2 = NEG_INF, m3 = NEG_INF;
        float l0 = 0.f, l1 = 0.f, l2 = 0.f, l3 = 0.f;
        for (int i = lane; i < deg; i += 32) {
            int s = __ldg(&csrsrc[beg + i]);
            float4 a = __ldg((const float4*)&el[s * 4]);
            OSM_STEP(m0, l0, lrelu(a.x + erv.x));
            OSM_STEP(m1, l1, lrelu(a.y + erv.y));
            OSM_STEP(m2, l2, lrelu(a.z + erv.z));
            OSM_STEP(m3, l3, lrelu(a.w + erv.w));
        }
#pragma unroll
        for (int off = 16; off > 0; off >>= 1) {
            float om, ol;
            om = __shfl_xor_sync(0xFFFFFFFFu, m0, off); ol = __shfl_xor_sync(0xFFFFFFFFu, l0, off);
            OSM_MERGE(m0, l0, om, ol);
            om = __shfl_xor_sync(0xFFFFFFFFu, m1, off); ol = __shfl_xor_sync(0xFFFFFFFFu, l1, off);
            OSM_MERGE(m1, l1, om, ol);
            om = __shfl_xor_sync(0xFFFFFFFFu, m2, off); ol = __shfl_xor_sync(0xFFFFFFFFu, l2, off);
            OSM_MERGE(m2, l2, om, ol);
            om = __shfl_xor_sync(0xFFFFFFFFu, m3, off); ol = __shfl_xor_sync(0xFFFFFFFFu, l3, off);
            OSM_MERGE(m3, l3, om, ol);
        }
        float r0 = 1.f / l0, r1 = 1.f / l1, r2 = 1.f / l2, r3 = 1.f / l3;

        int h0 = (lane * 4) / 40;
        int h1 = ((lane + 32) * 4) / 40;

        for (int base = 0; base < deg; base += CAP) {
            int cnt = min(CAP, deg - base);
            for (int i = lane; i < cnt; i += 32) {
                int s = __ldg(&csrsrc[beg + base + i]);
                float4 a = __ldg((const float4*)&el[s * 4]);
                float4 ex;
                ex.x = __expf(lrelu(a.x + erv.x) - m0) * r0;
                ex.y = __expf(lrelu(a.y + erv.y) - m1) * r1;
                ex.z = __expf(lrelu(a.z + erv.z) - m2) * r2;
                ex.w = __expf(lrelu(a.w + erv.w) - m3) * r3;
                s_ex[wid][i] = ex;
            }
            __syncwarp();
#pragma unroll 2
            for (int i = 0; i < cnt; i++) {
                int s = __ldg(&csrsrc[beg + base + i]);
                float4 ex4 = s_ex[wid][i];
                float a0 = (h0 == 0) ? ex4.x : (h0 == 1) ? ex4.y : (h0 == 2) ? ex4.z : ex4.w;
                float4 zv = __ldg((const float4*)&z[s * 160 + lane * 4]);
                acc0.x += a0 * zv.x;
                acc0.y += a0 * zv.y;
                acc0.z += a0 * zv.z;
                acc0.w += a0 * zv.w;
                if (lane < 8) {
                    float a1 = (h1 == 3) ? ex4.w : ex4.z;
                    float4 zw = __ldg((const float4*)&z[s * 160 + 128 + lane * 4]);
                    acc1.x += a1 * zw.x;
                    acc1.y += a1 * zw.y;
                    acc1.z += a1 * zw.z;
                    acc1.w += a1 * zw.w;
                }
            }
            __syncwarp();
        }
    }

    float4 o0 = *(const float4*)&lin[node * 160 + lane * 4];
    o0.x += acc0.x; o0.y += acc0.y; o0.z += acc0.z; o0.w += acc0.w;
    float4 o1 = make_float4(0.f, 0.f, 0.f, 0.f);
    if (lane < 8) {
        o1 = *(const float4*)&lin[node * 160 + 128 + lane * 4];
        o1.x += acc1.x; o1.y += acc1.y; o1.z += acc1.z; o1.w += acc1.w;
    }

    int i1 = lane + 10, i2 = lane + 20, i3a = lane + 30, i3b = (lane - 2) & 31;
    float4 v1, v2, v3a, v3b;
    v1.x = __shfl_sync(0xFFFFFFFFu, o0.x, i1); v1.y = __shfl_sync(0xFFFFFFFFu, o0.y, i1);
    v1.z = __shfl_sync(0xFFFFFFFFu, o0.z, i1); v1.w = __shfl_sync(0xFFFFFFFFu, o0.w, i1);
    v2.x = __shfl_sync(0xFFFFFFFFu, o0.x, i2); v2.y = __shfl_sync(0xFFFFFFFFu, o0.y, i2);
    v2.z = __shfl_sync(0xFFFFFFFFu, o0.z, i2); v2.w = __shfl_sync(0xFFFFFFFFu, o0.w, i2);
    v3a.x = __shfl_sync(0xFFFFFFFFu, o0.x, i3a); v3a.y = __shfl_sync(0xFFFFFFFFu, o0.y, i3a);
    v3a.z = __shfl_sync(0xFFFFFFFFu, o0.z, i3a); v3a.w = __shfl_sync(0xFFFFFFFFu, o0.w, i3a);
    v3b.x = __shfl_sync(0xFFFFFFFFu, o1.x, i3b); v3b.y = __shfl_sync(0xFFFFFFFFu, o1.y, i3b);
    v3b.z = __shfl_sync(0xFFFFFFFFu, o1.z, i3b); v3b.w = __shfl_sync(0xFFFFFFFFu, o1.w, i3b);
    if (lane < 10) {
        float4 v3 = (lane < 2) ? v3a : v3b;
        float4 bl = *(const float4*)&bias_last[lane * 4];
        float4 r;
        r.x = 0.25f * (o0.x + v1.x + v2.x + v3.x) + bl.x;
        r.y = 0.25f * (o0.y + v1.y + v2.y + v3.y) + bl.y;
        r.z = 0.25f * (o0.z + v1.z + v2.z + v3.z) + bl.z;
        r.w = 0.25f * (o0.w + v1.w + v2.w + v3.w) + bl.w;
        *(float4*)&outF[node * 40 + lane * 4] = r;
    }
}

// ---------------------------------------------------------------------------
extern "C" void kernel_launch(void* const* d_in, const int* in_sizes, int n_in,
                              void* d_out, int out_size) {
    const float* feat = (const float*)d_in[0];
    const int* src = (const int*)d_in[1];
    const int* dst = (const int*)d_in[2];
    const float* Wc[3] = {(const float*)d_in[3], (const float*)d_in[8], (const float*)d_in[13]};
    const float* al[3] = {(const float*)d_in[4], (const float*)d_in[9], (const float*)d_in[14]};
    const float* ar[3] = {(const float*)d_in[5], (const float*)d_in[10], (const float*)d_in[15]};
    const float* bc[3] = {(const float*)d_in[6], (const float*)d_in[11], (const float*)d_in[16]};
    const float* Wl[3] = {(const float*)d_in[7], (const float*)d_in[12], (const float*)d_in[17]};
    const float* g0 = (const float*)d_in[18];
    const float* b0 = (const float*)d_in[19];
    const float* g1 = (const float*)d_in[20];
    const float* b1 = (const float*)d_in[21];
    const float* bias_last = (const float*)d_in[22];

    const int n = in_sizes[0] / 128;  // 50000
    const int E = in_sizes[1];        // 800000

    float *z, *bufA, *bufB, *el, *er, *bnA, *bnB;
    int *deg, *rowptr, *wcur, *csrsrc, *bsum;
    __nv_bfloat16 *wthi, *wtlo;
    cudaGetSymbolAddress((void**)&z, g_z);
    cudaGetSymbolAddress((void**)&bufA, g_bufA);
    cudaGetSymbolAddress((void**)&bufB, g_bufB);
    cudaGetSymbolAddress((void**)&el, g_el);
    cudaGetSymbolAddress((void**)&er, g_er);
    cudaGetSymbolAddress((void**)&bnA, g_bnsumA);
    cudaGetSymbolAddress((void**)&bnB, g_bnsumB);
    cudaGetSymbolAddress((void**)&deg, g_deg);
    cudaGetSymbolAddress((void**)&rowptr, g_rowptr);
    cudaGetSymbolAddress((void**)&wcur, g_wcur);
    cudaGetSymbolAddress((void**)&csrsrc, g_csrsrc);
    cudaGetSymbolAddress((void**)&bsum, g_bsum);
    cudaGetSymbolAddress((void**)&wthi, g_wthi);
    cudaGetSymbolAddress((void**)&wtlo, g_wtlo);

    const int edge_blocks = (E + 255) / 256;
    const int agg_blocks = (n + 7) / 8;
    const int gemm_grid = (n + 127) / 128;
    const int nb = (n + 1023) / 1024;

    const int smem128 = (256 + 256) * 136 * 2;  // 139264
    const int smem160 = (256 + 320) * 136 * 2;  // 156672
    cudaFuncSetAttribute(gemm_dual<128, 32, false>, cudaFuncAttributeMaxDynamicSharedMemorySize, smem128);
    cudaFuncSetAttribute(gemm_dual<128, 32, true>, cudaFuncAttributeMaxDynamicSharedMemorySize, smem128);
    cudaFuncSetAttribute(gemm_dual<160, 40, true>, cudaFuncAttributeMaxDynamicSharedMemorySize, smem160);

    wsplit_all<<<(106496 + 255) / 256, 256>>>(Wc[0], Wl[0], Wc[1], Wl[1], Wc[2], Wl[2],
                                              wthi, wtlo, deg, bnA, bnB, n);
    count_kernel<<<edge_blocks, 256>>>(dst, deg, E);
    scan_partial<<<nb, 1024>>>(deg, rowptr, bsum, n);
    scan_add<<<nb, 1024>>>(rowptr, bsum, wcur, n, nb);

    gemm_dual<128, 32, false><<<gemm_grid, 256, smem128>>>(
        feat, wthi + 0 * WS, wtlo + 0 * WS, wthi + 1 * WS, wtlo + 1 * WS, bc[0],
        nullptr, nullptr, nullptr, z, bufA, al[0], ar[0], el, er, n);

    scatter_kernel<<<edge_blocks, 256>>>(src, dst, wcur, csrsrc, E);

    node_agg_kernel<<<agg_blocks, 256>>>(rowptr, csrsrc, el, er, z, bufA, bnA, n);

    gemm_dual<128, 32, true><<<gemm_grid, 256, smem128>>>(
        bufA, wthi + 2 * WS, wtlo + 2 * WS, wthi + 3 * WS, wtlo + 3 * WS, bc[1],
        bnA, g0, b0, z, bufB, al[1], ar[1], el, er, n);
    node_agg_kernel<<<agg_blocks, 256>>>(rowptr, csrsrc, el, er, z, bufB, bnB, n);

    gemm_dual<160, 40, true><<<gemm_grid, 256, smem160>>>(
        bufB, wthi + 4 * WS, wtlo + 4 * WS, wthi + 5 * WS, wtlo + 5 * WS, bc[2],
        bnB, g1, b1, z, bufA, al[2], ar[2], el, er, n);
    node_agg_final<<<agg_blocks, 256>>>(rowptr, csrsrc, el, er, z, bufA, bias_last,
                                        (float*)d_out, n);
}

// round 16
// speedup vs baseline: 1.0793x; 1.0382x over previous
#include <cuda_runtime.h>
#include <cuda_bf16.h>
#include <cstdint>

// ---------------------------------------------------------------------------
// GAT R14: mainloop fragment reuse — single ks loop, Bh reused across
// (Ah*Bh),(Al*Bh); Ah reused across (Ah*Bh),(Ah*Bl). ~30% fewer LDSM issues.
// Core = R13 (514.6us).
// ---------------------------------------------------------------------------

#define NMAX 50000
#define EMAX 800000
#define SLOPE 0.2f
#define BN_EPS 1e-5f
#define NEG_INF (-1e30f)
#define WS (160 * 128)

// ---------------- scratch ----------------
__device__ __align__(16) float g_z  [NMAX * 160];
__device__ __align__(16) float g_bufA[NMAX * 160];
__device__ __align__(16) float g_bufB[NMAX * 128];
__device__ __align__(16) float g_el [NMAX * 4];
__device__ __align__(16) float g_er [NMAX * 4];
__device__ __align__(16) float g_bnsumA[256];
__device__ __align__(16) float g_bnsumB[256];
__device__ int g_deg[NMAX];
__device__ int g_rowptr[NMAX + 1];
__device__ int g_wcur[NMAX];
__device__ int g_csrsrc[EMAX];
__device__ int g_bsum[64];
__device__ __align__(16) __nv_bfloat16 g_wthi[6][WS];
__device__ __align__(16) __nv_bfloat16 g_wtlo[6][WS];

__device__ __forceinline__ uint32_t smem_u32(const void* p) {
    uint32_t a;
    asm("{ .reg .u64 t; cvta.to.shared.u64 t, %1; cvt.u32.u64 %0, t; }" : "=r"(a) : "l"(p));
    return a;
}
__device__ __forceinline__ float lrelu(float x) { return x >= 0.f ? x : SLOPE * x; }

__device__ __forceinline__ void ldmx4(uint32_t* r, uint32_t addr) {
    asm volatile("ldmatrix.sync.aligned.m8n8.x4.shared.b16 {%0,%1,%2,%3}, [%4];"
                 : "=r"(r[0]), "=r"(r[1]), "=r"(r[2]), "=r"(r[3]) : "r"(addr));
}
__device__ __forceinline__ void mma16816(float* c, const uint32_t* a, const uint32_t* b) {
    asm volatile(
        "mma.sync.aligned.m16n8k16.row.col.f32.bf16.bf16.f32 "
        "{%0,%1,%2,%3}, {%4,%5,%6,%7}, {%8,%9}, {%0,%1,%2,%3};"
        : "+f"(c[0]), "+f"(c[1]), "+f"(c[2]), "+f"(c[3])
        : "r"(a[0]), "r"(a[1]), "r"(a[2]), "r"(a[3]), "r"(b[0]), "r"(b[1]));
}

// ================= wsplit_all =================
__global__ void wsplit_all(const float* __restrict__ W0, const float* __restrict__ W1,
                           const float* __restrict__ W2, const float* __restrict__ W3,
                           const float* __restrict__ W4, const float* __restrict__ W5,
                           __nv_bfloat16* __restrict__ hi, __nv_bfloat16* __restrict__ lo,
                           int* __restrict__ deg, float* __restrict__ bnA,
                           float* __restrict__ bnB, int n) {
    int i = blockIdx.x * blockDim.x + threadIdx.x;
    if (i < n) deg[i] = 0;
    if (i < 256) { bnA[i] = 0.f; bnB[i] = 0.f; }
    if (i < 106496) {
        int m, base, N;
        if (i < 65536)      { m = i >> 14; base = m << 14; N = 128; }
        else if (i < 86016) { m = 4; base = 65536; N = 160; }
        else                { m = 5; base = 86016; N = 160; }
        int k = i - base;
        int nn = k >> 7, kk = k & 127;
        const float* W = (m == 0) ? W0 : (m == 1) ? W1 : (m == 2) ? W2
                       : (m == 3) ? W3 : (m == 4) ? W4 : W5;
        float v = W[kk * N + nn];
        __nv_bfloat16 h = __float2bfloat16(v);
        hi[m * WS + k] = h;
        lo[m * WS + k] = __float2bfloat16(v - __bfloat162float(h));
    }
}

// ================= dual GEMM (fragment-reuse mainloop) =================
template <int N, int FOUT, bool BNIN>
__global__ void __launch_bounds__(256, 1)
gemm_dual(const float* __restrict__ X,
          const __nv_bfloat16* __restrict__ Bc_hi, const __nv_bfloat16* __restrict__ Bc_lo,
          const __nv_bfloat16* __restrict__ Bl_hi, const __nv_bfloat16* __restrict__ Bl_lo,
          const float* __restrict__ bcbias,
          const float* __restrict__ bnsum, const float* __restrict__ bng,
          const float* __restrict__ bnb,
          float* __restrict__ z, float* __restrict__ out,
          const float* __restrict__ al, const float* __restrict__ ar,
          float* __restrict__ el, float* __restrict__ er, int n) {
    constexpr int LDA = 136;
    constexpr int NF = N / 16;
    extern __shared__ __align__(16) char smem[];
    __nv_bfloat16* sAh = (__nv_bfloat16*)smem;
    __nv_bfloat16* sAl = sAh + 128 * LDA;
    __nv_bfloat16* sBh = sAl + 128 * LDA;
    __nv_bfloat16* sBl = sBh + N * LDA;
    __shared__ float s_bn[256];

    const int tid = threadIdx.x;
    const int wid = tid >> 5;
    const int lane = tid & 31;
    const int wm = wid & 3;
    const int wn = wid >> 2;
    const int quad = lane >> 2, tq = lane & 3;
    const int row0 = blockIdx.x * 128;

    if (BNIN) {
        if (tid < 128) {
            float inv_n = 1.f / (float)n;
            float mean = bnsum[tid] * inv_n;
            float var = bnsum[128 + tid] * inv_n - mean * mean;
            float s = bng[tid] * rsqrtf(var + BN_EPS);
            s_bn[tid] = s;
            s_bn[128 + tid] = bnb[tid] - mean * s;
        }
        __syncthreads();
    }

    // ---- fill A ----
    for (int idx = tid; idx < 128 * 32; idx += 256) {
        int r = idx >> 5, c4 = idx & 31;
        int gr = row0 + r;
        float4 v = make_float4(0.f, 0.f, 0.f, 0.f);
        if (gr < n) {
            v = *(const float4*)&X[gr * 128 + c4 * 4];
            if (BNIN) {
                int c = c4 * 4;
                v.x = fmaxf(0.f, fmaf(v.x, s_bn[c + 0], s_bn[128 + c + 0]));
                v.y = fmaxf(0.f, fmaf(v.y, s_bn[c + 1], s_bn[128 + c + 1]));
                v.z = fmaxf(0.f, fmaf(v.z, s_bn[c + 2], s_bn[128 + c + 2]));
                v.w = fmaxf(0.f, fmaf(v.w, s_bn[c + 3], s_bn[128 + c + 3]));
            }
        }
        __nv_bfloat162 h01, h23, l01, l23;
        h01.x = __float2bfloat16(v.x); l01.x = __float2bfloat16(v.x - __bfloat162float(h01.x));
        h01.y = __float2bfloat16(v.y); l01.y = __float2bfloat16(v.y - __bfloat162float(h01.y));
        h23.x = __float2bfloat16(v.z); l23.x = __float2bfloat16(v.z - __bfloat162float(h23.x));
        h23.y = __float2bfloat16(v.w); l23.y = __float2bfloat16(v.w - __bfloat162float(h23.y));
        uint2 hu, lu;
        hu.x = *(uint32_t*)&h01; hu.y = *(uint32_t*)&h23;
        lu.x = *(uint32_t*)&l01; lu.y = *(uint32_t*)&l23;
        *(uint2*)&sAh[r * LDA + c4 * 4] = hu;
        *(uint2*)&sAl[r * LDA + c4 * 4] = lu;
    }
    // ---- fill B = Wc ----
    for (int idx = tid; idx < N * 16; idx += 256) {
        int r = idx >> 4, c = idx & 15;
        *(uint4*)&sBh[r * LDA + c * 8] = *(const uint4*)&Bc_hi[r * 128 + c * 8];
        *(uint4*)&sBl[r * LDA + c * 8] = *(const uint4*)&Bc_lo[r * 128 + c * 8];
    }
    __syncthreads();

    const uint32_t uAh = smem_u32(sAh), uAl = smem_u32(sAl);
    const uint32_t uBh = smem_u32(sBh), uBl = smem_u32(sBl);
    const int arow = wm * 32 + (lane & 15);
    const int acol8 = (lane >> 4) * 8;
    const int browx = wn * (N / 2) + (lane & 7) + ((lane >> 4) & 1) * 8;
    const int bcol8 = ((lane >> 3) & 1) * 8;

    float c[2][NF][4];

    // fragment-reuse mainloop: per ks, 4 A-x4 loads + NF B-x4 loads, 3 mma sets.
#define RUN_MAINLOOP()                                                                      \
    _Pragma("unroll")                                                                       \
    for (int ks = 0; ks < 8; ks++) {                                                        \
        uint32_t ah[2][4], alr[2][4];                                                       \
        uint32_t bh[NF][2], bl[NF][2];                                                      \
        _Pragma("unroll")                                                                   \
        for (int i = 0; i < 2; i++)                                                         \
            ldmx4(ah[i], uAh + (uint32_t)(((arow + i * 16) * LDA + ks * 16 + acol8) * 2));  \
        _Pragma("unroll")                                                                   \
        for (int j = 0; j < NF; j += 2) {                                                   \
            uint32_t r4[4];                                                                 \
            ldmx4(r4, uBh + (uint32_t)(((browx + j * 8) * LDA + ks * 16 + bcol8) * 2));     \
            bh[j][0] = r4[0]; bh[j][1] = r4[1];                                             \
            bh[j + 1][0] = r4[2]; bh[j + 1][1] = r4[3];                                     \
        }                                                                                   \
        _Pragma("unroll")                                                                   \
        for (int i = 0; i < 2; i++)                                                         \
            _Pragma("unroll")                                                               \
            for (int j = 0; j < NF; j++) mma16816(c[i][j], ah[i], bh[j]);                   \
        _Pragma("unroll")                                                                   \
        for (int i = 0; i < 2; i++)                                                         \
            ldmx4(alr[i], uAl + (uint32_t)(((arow + i * 16) * LDA + ks * 16 + acol8) * 2)); \
        _Pragma("unroll")                                                                   \
        for (int i = 0; i < 2; i++)                                                         \
            _Pragma("unroll")                                                               \
            for (int j = 0; j < NF; j++) mma16816(c[i][j], alr[i], bh[j]);                  \
        _Pragma("unroll")                                                                   \
        for (int j = 0; j < NF; j += 2) {                                                   \
            uint32_t r4[4];                                                                 \
            ldmx4(r4, uBl + (uint32_t)(((browx + j * 8) * LDA + ks * 16 + bcol8) * 2));     \
            bl[j][0] = r4[0]; bl[j][1] = r4[1];                                             \
            bl[j + 1][0] = r4[2]; bl[j + 1][1] = r4[3];                                     \
        }                                                                                   \
        _Pragma("unroll")                                                                   \
        for (int i = 0; i < 2; i++)                                                         \
            _Pragma("unroll")                                                               \
            for (int j = 0; j < NF; j++) mma16816(c[i][j], ah[i], bl[j]);                   \
    }

    // =================== PHASE 1: z = X @ Wc ===================
#pragma unroll
    for (int i = 0; i < 2; i++)
#pragma unroll
        for (int j = 0; j < NF; j++)
#pragma unroll
            for (int k = 0; k < 4; k++) c[i][j][k] = 0.f;

    RUN_MAINLOOP()

    // store z + el/er from accumulators
    float elp[4][2], erp[4][2];
#pragma unroll
    for (int s = 0; s < 4; s++) { elp[s][0] = elp[s][1] = erp[s][0] = erp[s][1] = 0.f; }
#pragma unroll
    for (int i = 0; i < 2; i++) {
#pragma unroll
        for (int half = 0; half < 2; half++) {
            int r = row0 + wm * 32 + i * 16 + quad + half * 8;
            if (r < n) {
#pragma unroll
                for (int j = 0; j < NF; j++) {
                    int col = wn * (N / 2) + j * 8 + tq * 2;
                    float v0 = c[i][j][half * 2], v1 = c[i][j][half * 2 + 1];
                    *(float2*)&z[r * N + col] = make_float2(v0, v1);
                    int hloc = (j * 8) / FOUT;
                    elp[i * 2 + half][hloc] += v0 * __ldg(&al[col]) + v1 * __ldg(&al[col + 1]);
                    erp[i * 2 + half][hloc] += v0 * __ldg(&ar[col]) + v1 * __ldg(&ar[col + 1]);
                }
            }
        }
    }
#pragma unroll
    for (int s = 0; s < 4; s++) {
#pragma unroll
        for (int h = 0; h < 2; h++) {
            float e = elp[s][h], f = erp[s][h];
            e += __shfl_xor_sync(0xFFFFFFFFu, e, 1);
            e += __shfl_xor_sync(0xFFFFFFFFu, e, 2);
            f += __shfl_xor_sync(0xFFFFFFFFu, f, 1);
            f += __shfl_xor_sync(0xFFFFFFFFu, f, 2);
            if (tq == 0) {
                int i = s >> 1, half = s & 1;
                int r = row0 + wm * 32 + i * 16 + quad + half * 8;
                if (r < n) {
                    int hg = wn * 2 + h;
                    el[r * 4 + hg] = e;
                    er[r * 4 + hg] = f;
                }
            }
        }
    }
    __syncthreads();

    // ---- fill B = Wl ----
    for (int idx = tid; idx < N * 16; idx += 256) {
        int r = idx >> 4, cc = idx & 15;
        *(uint4*)&sBh[r * LDA + cc * 8] = *(const uint4*)&Bl_hi[r * 128 + cc * 8];
        *(uint4*)&sBl[r * LDA + cc * 8] = *(const uint4*)&Bl_lo[r * 128 + cc * 8];
    }
    __syncthreads();

    // =================== PHASE 2: out = X @ Wl + bc ===================
#pragma unroll
    for (int i = 0; i < 2; i++)
#pragma unroll
        for (int j = 0; j < NF; j++)
#pragma unroll
            for (int k = 0; k < 4; k++) c[i][j][k] = 0.f;

    RUN_MAINLOOP()

#pragma unroll
    for (int i = 0; i < 2; i++) {
#pragma unroll
        for (int half = 0; half < 2; half++) {
            int r = row0 + wm * 32 + i * 16 + quad + half * 8;
            if (r < n) {
#pragma unroll
                for (int j = 0; j < NF; j++) {
                    int col = wn * (N / 2) + j * 8 + tq * 2;
                    float2 v = make_float2(c[i][j][half * 2] + __ldg(&bcbias[col]),
                                           c[i][j][half * 2 + 1] + __ldg(&bcbias[col + 1]));
                    *(float2*)&out[r * N + col] = v;
                }
            }
        }
    }
#undef RUN_MAINLOOP
}

// ================= CSR build =================
__global__ void count_kernel(const int* __restrict__ dst, int* __restrict__ deg, int E) {
    int e = blockIdx.x * blockDim.x + threadIdx.x;
    if (e < E) atomicAdd(&deg[dst[e]], 1);
}
__global__ void scan_partial(const int* __restrict__ deg, int* __restrict__ rowptr,
                             int* __restrict__ bsum, int n) {
    __shared__ int sdata[1024];
    int tid = threadIdx.x;
    int i = blockIdx.x * 1024 + tid;
    int v = (i < n) ? deg[i] : 0;
    sdata[tid] = v;
    __syncthreads();
    for (int off = 1; off < 1024; off <<= 1) {
        int t = (tid >= off) ? sdata[tid - off] : 0;
        __syncthreads();
        sdata[tid] += t;
        __syncthreads();
    }
    if (i < n) rowptr[i] = sdata[tid] - v;
    if (tid == 1023) bsum[blockIdx.x] = sdata[1023];
}
__global__ void scan_add(int* __restrict__ rowptr, const int* __restrict__ bsum,
                         int* __restrict__ wcur, int n, int nb) {
    __shared__ int s_bs[64];
    int t = threadIdx.x;
    if (t < 64) s_bs[t] = (t < nb) ? bsum[t] : 0;
    __syncthreads();
    for (int off = 1; off < 64; off <<= 1) {
        int u = (t < 64 && t >= off) ? s_bs[t - off] : 0;
        __syncthreads();
        if (t < 64) s_bs[t] += u;
        __syncthreads();
    }
    int pref = (blockIdx.x == 0) ? 0 : s_bs[blockIdx.x - 1];
    int i = blockIdx.x * 1024 + t;
    if (i < n) {
        int v = rowptr[i] + pref;
        rowptr[i] = v;
        wcur[i] = v;
    }
    if (i == 0) rowptr[n] = s_bs[nb - 1];
}
__global__ void scatter_kernel(const int* __restrict__ src, const int* __restrict__ dst,
                               int* __restrict__ wcur, int* __restrict__ csrsrc, int E) {
    int e = blockIdx.x * blockDim.x + threadIdx.x;
    if (e < E) {
        int pos = atomicAdd(&wcur[dst[e]], 1);
        csrsrc[pos] = src[e];
    }
}

// ================= online-softmax helpers =================
#define OSM_STEP(m, l, e)                                  \
    do {                                                   \
        float _nm = fmaxf(m, e);                           \
        l = l * __expf(m - _nm) + __expf(e - _nm);         \
        m = _nm;                                           \
    } while (0)
#define OSM_MERGE(m, l, om, ol)                            \
    do {                                                   \
        float _nm = fmaxf(m, om);                          \
        l = l * __expf(m - _nm) + ol * __expf(om - _nm);   \
        m = _nm;                                           \
    } while (0)

// ================= node_agg (layers 0/1): KOUT=128 + fused BN stats =========
__global__ void node_agg_kernel(const int* __restrict__ rowptr, const int* __restrict__ csrsrc,
                                const float* __restrict__ el, const float* __restrict__ er,
                                const float* __restrict__ z, float* __restrict__ out,
                                float* __restrict__ bnsum, int n) {
    constexpr int WARPS = 8;
    constexpr int CAP = 64;
    __shared__ __align__(16) float4 s_ex[WARPS][CAP];
    __shared__ float sred[256];

    int tid = threadIdx.x;
    int wid = tid >> 5;
    int lane = tid & 31;
    int node = blockIdx.x * WARPS + wid;

    if (tid < 256) sred[tid] = 0.f;
    __syncthreads();

    bool active = node < n;
    int beg = 0, deg = 0;
    if (active) {
        beg = rowptr[node];
        deg = rowptr[node + 1] - beg;
    }

    float4 acc = make_float4(0.f, 0.f, 0.f, 0.f);
    if (active && deg > 0) {
        float4 erv = *(const float4*)&er[node * 4];
        float m0 = NEG_INF, m1 = NEG_INF, m2 = NEG_INF, m3 = NEG_INF;
        float l0 = 0.f, l1 = 0.f, l2 = 0.f, l3 = 0.f;
        for (int i = lane; i < deg; i += 32) {
            int s = __ldg(&csrsrc[beg + i]);
            float4 a = __ldg((const float4*)&el[s * 4]);
            OSM_STEP(m0, l0, lrelu(a.x + erv.x));
            OSM_STEP(m1, l1, lrelu(a.y + erv.y));
            OSM_STEP(m2, l2, lrelu(a.z + erv.z));
            OSM_STEP(m3, l3, lrelu(a.w + erv.w));
        }
#pragma unroll
        for (int off = 16; off > 0; off >>= 1) {
            float om, ol;
            om = __shfl_xor_sync(0xFFFFFFFFu, m0, off); ol = __shfl_xor_sync(0xFFFFFFFFu, l0, off);
            OSM_MERGE(m0, l0, om, ol);
            om = __shfl_xor_sync(0xFFFFFFFFu, m1, off); ol = __shfl_xor_sync(0xFFFFFFFFu, l1, off);
            OSM_MERGE(m1, l1, om, ol);
            om = __shfl_xor_sync(0xFFFFFFFFu, m2, off); ol = __shfl_xor_sync(0xFFFFFFFFu, l2, off);
            OSM_MERGE(m2, l2, om, ol);
            om = __shfl_xor_sync(0xFFFFFFFFu, m3, off); ol = __shfl_xor_sync(0xFFFFFFFFu, l3, off);
            OSM_MERGE(m3, l3, om, ol);
        }
        float r0 = 1.f / l0, r1 = 1.f / l1, r2 = 1.f / l2, r3 = 1.f / l3;
        int h = lane >> 3;

        for (int base = 0; base < deg; base += CAP) {
            int cnt = min(CAP, deg - base);
            for (int i = lane; i < cnt; i += 32) {
                int s = __ldg(&csrsrc[beg + base + i]);
                float4 a = __ldg((const float4*)&el[s * 4]);
                float4 ex;
                ex.x = __expf(lrelu(a.x + erv.x) - m0) * r0;
                ex.y = __expf(lrelu(a.y + erv.y) - m1) * r1;
                ex.z = __expf(lrelu(a.z + erv.z) - m2) * r2;
                ex.w = __expf(lrelu(a.w + erv.w) - m3) * r3;
                s_ex[wid][i] = ex;
            }
            __syncwarp();
#pragma unroll 2
            for (int i = 0; i < cnt; i++) {
                int s = __ldg(&csrsrc[beg + base + i]);
                float4 ex4 = s_ex[wid][i];
                float a = (h == 0) ? ex4.x : (h == 1) ? ex4.y : (h == 2) ? ex4.z : ex4.w;
                float4 zv = __ldg((const float4*)&z[s * 128 + lane * 4]);
                acc.x += a * zv.x;
                acc.y += a * zv.y;
                acc.z += a * zv.z;
                acc.w += a * zv.w;
            }
            __syncwarp();
        }
    }

    float4 o = make_float4(0.f, 0.f, 0.f, 0.f);
    if (active) {
        o = *(float4*)&out[node * 128 + lane * 4];
        o.x += acc.x; o.y += acc.y; o.z += acc.z; o.w += acc.w;
        if (deg > 0) *(float4*)&out[node * 128 + lane * 4] = o;
    }

    if (active) {
        int c = lane * 4;
        atomicAdd(&sred[c + 0], o.x);
        atomicAdd(&sred[c + 1], o.y);
        atomicAdd(&sred[c + 2], o.z);
        atomicAdd(&sred[c + 3], o.w);
        atomicAdd(&sred[128 + c + 0], o.x * o.x);
        atomicAdd(&sred[128 + c + 1], o.y * o.y);
        atomicAdd(&sred[128 + c + 2], o.z * o.z);
        atomicAdd(&sred[128 + c + 3], o.w * o.w);
    }
    __syncthreads();
    if (tid < 128) {
        atomicAdd(&bnsum[tid], sred[tid]);
        atomicAdd(&bnsum[128 + tid], sred[128 + tid]);
    }
}

// ================= node_agg_final (layer 2): KOUT=160 + head-mean -> d_out ===
__global__ void node_agg_final(const int* __restrict__ rowptr, const int* __restrict__ csrsrc,
                               const float* __restrict__ el, const float* __restrict__ er,
                               const float* __restrict__ z, const float* __restrict__ lin,
                               const float* __restrict__ bias_last, float* __restrict__ outF,
                               int n) {
    constexpr int WARPS = 8;
    constexpr int CAP = 64;
    __shared__ __align__(16) float4 s_ex[WARPS][CAP];

    int wid = threadIdx.x >> 5;
    int lane = threadIdx.x & 31;
    int node = blockIdx.x * WARPS + wid;
    if (node >= n) return;
    int beg = rowptr[node];
    int deg = rowptr[node + 1] - beg;

    float4 acc0 = make_float4(0.f, 0.f, 0.f, 0.f);
    float4 acc1 = make_float4(0.f, 0.f, 0.f, 0.f);

    if (deg > 0) {
        float4 erv = *(const float4*)&er[node * 4];
        float m0 = NEG_INF, m1 = NEG_INF, m2 = NEG_INF, m3 = NEG_INF;
        float l0 = 0.f, l1 = 0.f, l2 = 0.f, l3 = 0.f;
        for (int i = lane; i < deg; i += 32) {
            int s = __ldg(&csrsrc[beg + i]);
            float4 a = __ldg((const float4*)&el[s * 4]);
            OSM_STEP(m0, l0, lrelu(a.x + erv.x));
            OSM_STEP(m1, l1, lrelu(a.y + erv.y));
            OSM_STEP(m2, l2, lrelu(a.z + erv.z));
            OSM_STEP(m3, l3, lrelu(a.w + erv.w));
        }
#pragma unroll
        for (int off = 16; off > 0; off >>= 1) {
            float om, ol;
            om = __shfl_xor_sync(0xFFFFFFFFu, m0, off); ol = __shfl_xor_sync(0xFFFFFFFFu, l0, off);
            OSM_MERGE(m0, l0, om, ol);
            om = __shfl_xor_sync(0xFFFFFFFFu, m1, off); ol = __shfl_xor_sync(0xFFFFFFFFu, l1, off);
            OSM_MERGE(m1, l1, om, ol);
            om = __shfl_xor_sync(0xFFFFFFFFu, m2, off); ol = __shfl_xor_sync(0xFFFFFFFFu, l2, off);
            OSM_MERGE(m2, l2, om, ol);
            om = __shfl_xor_sync(0xFFFFFFFFu, m3, off); ol = __shfl_xor_sync(0xFFFFFFFFu, l3, off);
            OSM_MERGE(m3, l3, om, ol);
        }
        float r0 = 1.f / l0, r1 = 1.f / l1, r2 = 1.f / l2, r3 = 1.f / l3;

        int h0 = (lane * 4) / 40;
        int h1 = ((lane + 32) * 4) / 40;

        for (int base = 0; base < deg; base += CAP) {
            int cnt = min(CAP, deg - base);
            for (int i = lane; i < cnt; i += 32) {
                int s = __ldg(&csrsrc[beg + base + i]);
                float4 a = __ldg((const float4*)&el[s * 4]);
                float4 ex;
                ex.x = __expf(lrelu(a.x + erv.x) - m0) * r0;
                ex.y = __expf(lrelu(a.y + erv.y) - m1) * r1;
                ex.z = __expf(lrelu(a.z + erv.z) - m2) * r2;
                ex.w = __expf(lrelu(a.w + erv.w) - m3) * r3;
                s_ex[wid][i] = ex;
            }
            __syncwarp();
#pragma unroll 2
            for (int i = 0; i < cnt; i++) {
                int s = __ldg(&csrsrc[beg + base + i]);
                float4 ex4 = s_ex[wid][i];
                float a0 = (h0 == 0) ? ex4.x : (h0 == 1) ? ex4.y : (h0 == 2) ? ex4.z : ex4.w;
                float4 zv = __ldg((const float4*)&z[s * 160 + lane * 4]);
                acc0.x += a0 * zv.x;
                acc0.y += a0 * zv.y;
                acc0.z += a0 * zv.z;
                acc0.w += a0 * zv.w;
                if (lane < 8) {
                    float a1 = (h1 == 3) ? ex4.w : ex4.z;
                    float4 zw = __ldg((const float4*)&z[s * 160 + 128 + lane * 4]);
                    acc1.x += a1 * zw.x;
                    acc1.y += a1 * zw.y;
                    acc1.z += a1 * zw.z;
                    acc1.w += a1 * zw.w;
                }
            }
            __syncwarp();
        }
    }

    float4 o0 = *(const float4*)&lin[node * 160 + lane * 4];
    o0.x += acc0.x; o0.y += acc0.y; o0.z += acc0.z; o0.w += acc0.w;
    float4 o1 = make_float4(0.f, 0.f, 0.f, 0.f);
    if (lane < 8) {
        o1 = *(const float4*)&lin[node * 160 + 128 + lane * 4];
        o1.x += acc1.x; o1.y += acc1.y; o1.z += acc1.z; o1.w += acc1.w;
    }

    int i1 = lane + 10, i2 = lane + 20, i3a = lane + 30, i3b = (lane - 2) & 31;
    float4 v1, v2, v3a, v3b;
    v1.x = __shfl_sync(0xFFFFFFFFu, o0.x, i1); v1.y = __shfl_sync(0xFFFFFFFFu, o0.y, i1);
    v1.z = __shfl_sync(0xFFFFFFFFu, o0.z, i1); v1.w = __shfl_sync(0xFFFFFFFFu, o0.w, i1);
    v2.x = __shfl_sync(0xFFFFFFFFu, o0.x, i2); v2.y = __shfl_sync(0xFFFFFFFFu, o0.y, i2);
    v2.z = __shfl_sync(0xFFFFFFFFu, o0.z, i2); v2.w = __shfl_sync(0xFFFFFFFFu, o0.w, i2);
    v3a.x = __shfl_sync(0xFFFFFFFFu, o0.x, i3a); v3a.y = __shfl_sync(0xFFFFFFFFu, o0.y, i3a);
    v3a.z = __shfl_sync(0xFFFFFFFFu, o0.z, i3a); v3a.w = __shfl_sync(0xFFFFFFFFu, o0.w, i3a);
    v3b.x = __shfl_sync(0xFFFFFFFFu, o1.x, i3b); v3b.y = __shfl_sync(0xFFFFFFFFu, o1.y, i3b);
    v3b.z = __shfl_sync(0xFFFFFFFFu, o1.z, i3b); v3b.w = __shfl_sync(0xFFFFFFFFu, o1.w, i3b);
    if (lane < 10) {
        float4 v3 = (lane < 2) ? v3a : v3b;
        float4 bl4 = *(const float4*)&bias_last[lane * 4];
        float4 r;
        r.x = 0.25f * (o0.x + v1.x + v2.x + v3.x) + bl4.x;
        r.y = 0.25f * (o0.y + v1.y + v2.y + v3.y) + bl4.y;
        r.z = 0.25f * (o0.z + v1.z + v2.z + v3.z) + bl4.z;
        r.w = 0.25f * (o0.w + v1.w + v2.w + v3.w) + bl4.w;
        *(float4*)&outF[node * 40 + lane * 4] = r;
    }
}

// ---------------------------------------------------------------------------
extern "C" void kernel_launch(void* const* d_in, const int* in_sizes, int n_in,
                              void* d_out, int out_size) {
    const float* feat = (const float*)d_in[0];
    const int* src = (const int*)d_in[1];
    const int* dst = (const int*)d_in[2];
    const float* Wc[3] = {(const float*)d_in[3], (const float*)d_in[8], (const float*)d_in[13]};
    const float* al[3] = {(const float*)d_in[4], (const float*)d_in[9], (const float*)d_in[14]};
    const float* ar[3] = {(const float*)d_in[5], (const float*)d_in[10], (const float*)d_in[15]};
    const float* bc[3] = {(const float*)d_in[6], (const float*)d_in[11], (const float*)d_in[16]};
    const float* Wl[3] = {(const float*)d_in[7], (const float*)d_in[12], (const float*)d_in[17]};
    const float* g0 = (const float*)d_in[18];
    const float* b0 = (const float*)d_in[19];
    const float* g1 = (const float*)d_in[20];
    const float* b1 = (const float*)d_in[21];
    const float* bias_last = (const float*)d_in[22];

    const int n = in_sizes[0] / 128;  // 50000
    const int E = in_sizes[1];        // 800000

    float *z, *bufA, *bufB, *el, *er, *bnA, *bnB;
    int *deg, *rowptr, *wcur, *csrsrc, *bsum;
    __nv_bfloat16 *wthi, *wtlo;
    cudaGetSymbolAddress((void**)&z, g_z);
    cudaGetSymbolAddress((void**)&bufA, g_bufA);
    cudaGetSymbolAddress((void**)&bufB, g_bufB);
    cudaGetSymbolAddress((void**)&el, g_el);
    cudaGetSymbolAddress((void**)&er, g_er);
    cudaGetSymbolAddress((void**)&bnA, g_bnsumA);
    cudaGetSymbolAddress((void**)&bnB, g_bnsumB);
    cudaGetSymbolAddress((void**)&deg, g_deg);
    cudaGetSymbolAddress((void**)&rowptr, g_rowptr);
    cudaGetSymbolAddress((void**)&wcur, g_wcur);
    cudaGetSymbolAddress((void**)&csrsrc, g_csrsrc);
    cudaGetSymbolAddress((void**)&bsum, g_bsum);
    cudaGetSymbolAddress((void**)&wthi, g_wthi);
    cudaGetSymbolAddress((void**)&wtlo, g_wtlo);

    const int edge_blocks = (E + 255) / 256;
    const int agg_blocks = (n + 7) / 8;
    const int gemm_grid = (n + 127) / 128;
    const int nb = (n + 1023) / 1024;

    const int smem128 = (256 + 256) * 136 * 2;  // 139264
    const int smem160 = (256 + 320) * 136 * 2;  // 156672
    cudaFuncSetAttribute(gemm_dual<128, 32, false>, cudaFuncAttributeMaxDynamicSharedMemorySize, smem128);
    cudaFuncSetAttribute(gemm_dual<128, 32, true>, cudaFuncAttributeMaxDynamicSharedMemorySize, smem128);
    cudaFuncSetAttribute(gemm_dual<160, 40, true>, cudaFuncAttributeMaxDynamicSharedMemorySize, smem160);

    wsplit_all<<<(106496 + 255) / 256, 256>>>(Wc[0], Wl[0], Wc[1], Wl[1], Wc[2], Wl[2],
                                              wthi, wtlo, deg, bnA, bnB, n);
    count_kernel<<<edge_blocks, 256>>>(dst, deg, E);
    scan_partial<<<nb, 1024>>>(deg, rowptr, bsum, n);
    scan_add<<<nb, 1024>>>(rowptr, bsum, wcur, n, nb);

    gemm_dual<128, 32, false><<<gemm_grid, 256, smem128>>>(
        feat, wthi + 0 * WS, wtlo + 0 * WS, wthi + 1 * WS, wtlo + 1 * WS, bc[0],
        nullptr, nullptr, nullptr, z, bufA, al[0], ar[0], el, er, n);

    scatter_kernel<<<edge_blocks, 256>>>(src, dst, wcur, csrsrc, E);

    node_agg_kernel<<<agg_blocks, 256>>>(rowptr, csrsrc, el, er, z, bufA, bnA, n);

    gemm_dual<128, 32, true><<<gemm_grid, 256, smem128>>>(
        bufA, wthi + 2 * WS, wtlo + 2 * WS, wthi + 3 * WS, wtlo + 3 * WS, bc[1],
        bnA, g0, b0, z, bufB, al[1], ar[1], el, er, n);
    node_agg_kernel<<<agg_blocks, 256>>>(rowptr, csrsrc, el, er, z, bufB, bnB, n);

    gemm_dual<160, 40, true><<<gemm_grid, 256, smem160>>>(
        bufB, wthi + 4 * WS, wtlo + 4 * WS, wthi + 5 * WS, wtlo + 5 * WS, bc[2],
        bnB, g1, b1, z, bufA, al[2], ar[2], el, er, n);
    node_agg_final<<<agg_blocks, 256>>>(rowptr, csrsrc, el, er, z, bufA, bias_last,
                                        (float*)d_out, n);
}